// round 13
// baseline (speedup 1.0000x reference)
#include <cuda_runtime.h>
#include <cuda_bf16.h>
#include <math.h>

typedef unsigned long long ull;
typedef unsigned int uint;

#define NB   512
#define DM   128
#define DOUT 64
#define DP   32
#define NPIX 225
#define PSTR 228
#define PADP 292
#define XST  256
#define MAXF 31.75f
#define INV_MAXF (1.0f/31.75f)
#define MAXM (127.0f/3.515625f)

// interleaved hi/lo + k-permuted layout: row = 32 groups x (8B hi + 8B lo) + pad
#define XROW2 544                      // bytes per row
#define XT2D (289*XROW2)               // dirconv padded 17x17 tile: 157216
#define WT2  (128*XROW2)               // weight tile: 69632
#define SMD2 (XT2D + WT2)              // 226848
#define XP2  (256*XROW2)               // pw dense tile: 139264
#define SMP2 (XP2 + WT2)               // 208896
#define SMC (DM*XST*4 + DOUT*PADP*4)   // k_fin smem

// ---------------- device scratch ----------------
__device__ __align__(16) float g_xs [4ull*NB*DM*PSTR];
__device__ __align__(16) float g_tmp[4ull*NB*DM*PSTR];
// 18 matrices: 0..11 dconv l*3+t, 12..15 c1 l, 16 r0_w1, 17 r0_w2
// each [128 rows][272 bf16] in interleaved hi/lo permuted layout
__device__ __align__(16) __nv_bfloat16 g_w[18*128*272];
__device__ __align__(16) float g_wfn[DM*DOUT];    // fin [i][o]

__constant__ int c_dr[4][3] = {{0,0,0},{-1,0,1},{-1,0,1},{1,0,-1}};
__constant__ int c_dc[4][3] = {{-1,0,1},{0,0,0},{-1,0,1},{-1,0,1}};

// ---------------- helpers ----------------
__device__ __forceinline__ ull pack2(float lo, float hi) {
    ull r; asm("mov.b64 %0, {%1,%2};" : "=l"(r) : "f"(lo), "f"(hi)); return r;
}
__device__ __forceinline__ float2 unpack2(ull v) {
    float2 f; asm("mov.b64 {%0,%1}, %2;" : "=f"(f.x), "=f"(f.y) : "l"(v)); return f;
}
__device__ __forceinline__ ull fma2(ull a, ull b, ull c) {
    ull d; asm("fma.rn.f32x2 %0, %1, %2, %3;" : "=l"(d) : "l"(a), "l"(b), "l"(c)); return d;
}
__device__ __forceinline__ float silu(float x) {
    return __fdividef(x, 1.f + __expf(-x));
}
__device__ __forceinline__ void mma_bf16(float* c,
    uint a0, uint a1, uint a2, uint a3, uint b0, uint b1) {
    asm("mma.sync.aligned.m16n8k16.row.col.f32.bf16.bf16.f32 "
        "{%0,%1,%2,%3}, {%4,%5,%6,%7}, {%8,%9}, {%0,%1,%2,%3};"
        : "+f"(c[0]), "+f"(c[1]), "+f"(c[2]), "+f"(c[3])
        : "r"(a0), "r"(a1), "r"(a2), "r"(a3), "r"(b0), "r"(b1));
}
// k permutation: logical channel -> physical slot so that each thread's
// (k, k+8) fragment pairs are contiguous 4-bf16 groups.
__device__ __forceinline__ int kphys(int c) {
    int blk = c >> 4, r = c & 15;
    int hi = r >> 3, rl = r & 7;
    return blk * 16 + (rl >> 1) * 4 + hi * 2 + (rl & 1);
}
// byte offset within a row for physical slot p (hi element; lo is +8)
__device__ __forceinline__ int kbyte(int p) {
    return (p >> 2) * 16 + (p & 3) * 2;
}

// ---------------- weight prep: 18x f32 [o][128] -> interleaved hi/lo rows ----------------
__global__ void k_prep(const float* __restrict__ dconv,
                       const float* __restrict__ c1,
                       const float* __restrict__ r1,
                       const float* __restrict__ r2,
                       __nv_bfloat16* __restrict__ w) {
    int n = 18 * 128 * 128;
    char* wb = (char*)w;
    for (int idx = blockIdx.x * blockDim.x + threadIdx.x; idx < n;
         idx += gridDim.x * blockDim.x) {
        int m = idx / (128 * 128);
        int rem = idx - m * 128 * 128;
        int o = rem / 128, k = rem - o * 128;
        float v;
        if (m < 12)       v = dconv[(m * 128 + o) * 128 + k];
        else if (m < 16)  v = c1[((m - 12) * 128 + o) * 128 + k];
        else if (m == 16) v = r1[o * 128 + k];
        else              v = r2[o * 128 + k];
        __nv_bfloat16 hi = __float2bfloat16(v);
        __nv_bfloat16 lo = __float2bfloat16(v - __bfloat162float(hi));
        int p = kphys(k);
        size_t base = (size_t)(m * 128 + o) * XROW2 + kbyte(p);
        *(__nv_bfloat16*)(wb + base)     = hi;
        *(__nv_bfloat16*)(wb + base + 8) = lo;
    }
}

// ---------------- transpose fin weights: [o(64)][i(128)] -> [i][o] ----------------
__global__ void k_xpose_fin(const float* __restrict__ fin, float* __restrict__ wfn) {
    int n = DOUT * DM;
    for (int idx = blockIdx.x * blockDim.x + threadIdx.x; idx < n;
         idx += gridDim.x * blockDim.x) {
        int r = idx / DM, c = idx - r * DM;
        wfn[c * DOUT + r] = fin[idx];
    }
}

// ---------------- input map conv (2 -> 128) + silu ----------------
__global__ __launch_bounds__(256) void k_map(const float* __restrict__ x,
                                             const float* __restrict__ mw,
                                             const float* __restrict__ mb,
                                             float* __restrict__ xsb) {
    int b = blockIdx.x, d = blockIdx.y, tid = threadIdx.x;
    __shared__ float xp[2 * PADP];
    for (int i = tid; i < 2 * PADP; i += 256) xp[i] = 0.f;
    __syncthreads();
    const float* xb = x + (size_t)b * 2 * NPIX;
    for (int i = tid; i < 2 * NPIX; i += 256) {
        int c = i / NPIX, p = i - c * NPIX;
        int h = p / 15, w = p - h * 15;
        xp[c * PADP + (h + 1) * 17 + (w + 1)] = xb[i];
    }
    __syncthreads();
    int dr[3], dc[3];
#pragma unroll
    for (int t = 0; t < 3; t++) { dr[t] = c_dr[d][t]; dc[t] = c_dc[d][t]; }
    float* dst = xsb + (size_t)(d * NB + b) * DM * PSTR;
    for (int idx = tid; idx < DM * NPIX; idx += 256) {
        int o = idx / NPIX, p = idx - o * NPIX;
        int h = p / 15, w = p - h * 15;
        float acc = mb[o];
#pragma unroll
        for (int t = 0; t < 3; t++) {
            int off = (h + 1 + dr[t]) * 17 + (w + 1 + dc[t]);
            acc += mw[(t * DM + o) * 2 + 0] * xp[off]
                 + mw[(t * DM + o) * 2 + 1] * xp[PADP + off];
        }
        dst[o * PSTR + p] = silu(acc);
    }
}

// -------- tensor-core directional 3-tap conv 128->128 + silu --------
// Interleaved hi/lo permuted tiles; one LDS.128 per B-fragment-pair,
// two LDS.128 for all A-fragments.
__global__ __launch_bounds__(512, 1) void k_dirconv_mma(
    const float* __restrict__ srcb, float* __restrict__ dstb,
    const __nv_bfloat16* __restrict__ w,   // [3][128][272] interleaved
    const float* __restrict__ bias) {
    extern __shared__ char smem[];
    char* xt  = smem;              // XT2D
    char* wsm = smem + XT2D;       // WT2
    int b = blockIdx.x, d = blockIdx.y;
    int tid = threadIdx.x, lane = tid & 31, wid = tid >> 5;
    const float* src = srcb + (size_t)(d * NB + b) * DM * PSTR;
    float*       dst = dstb + (size_t)(d * NB + b) * DM * PSTR;

    for (int i = tid * 16; i < XT2D; i += 512 * 16)
        *(float4*)(xt + i) = make_float4(0.f, 0.f, 0.f, 0.f);
    __syncthreads();
    for (int idx = tid; idx < DM * NPIX; idx += 512) {
        int c = idx / NPIX, p = idx - c * NPIX;
        int h = p / 15, ww = p - h * 15;
        int rp = (h + 1) * 17 + (ww + 1);
        float v = src[c * PSTR + p];
        __nv_bfloat16 hi = __float2bfloat16(v);
        __nv_bfloat16 lo = __float2bfloat16(v - __bfloat162float(hi));
        int off = rp * XROW2 + kbyte(kphys(c));
        *(__nv_bfloat16*)(xt + off)     = hi;
        *(__nv_bfloat16*)(xt + off + 8) = lo;
    }

    const int g  = lane >> 2;
    const int t4 = lane & 3;
    const int mb = (wid & 7) * 16;
    const int nh = wid >> 3;

    int rowb[15];
#pragma unroll
    for (int nt = 0; nt < 15; nt++) {
        int p = (nh * 15 + nt) * 8 + g;
        int pc = (p < NPIX) ? p : (NPIX - 1);
        int h = pc / 15, ww = pc - h * 15;
        rowb[nt] = ((h + 1) * 17 + (ww + 1)) * XROW2;
    }

    float acc[15][4];
#pragma unroll
    for (int nt = 0; nt < 15; nt++) {
        acc[nt][0] = 0.f; acc[nt][1] = 0.f; acc[nt][2] = 0.f; acc[nt][3] = 0.f;
    }

    int dlt[3];
#pragma unroll
    for (int t = 0; t < 3; t++) dlt[t] = (c_dr[d][t] * 17 + c_dc[d][t]) * XROW2;

    for (int tp = 0; tp < 3; tp++) {
        __syncthreads();
        {
            const float4* ws = (const float4*)((const char*)w + (size_t)tp * WT2);
            float4* wd = (float4*)wsm;
            for (int i = tid; i < WT2 / 16; i += 512) wd[i] = ws[i];
        }
        __syncthreads();
        const int dl0 = dlt[tp];

#pragma unroll
        for (int ks = 0; ks < 8; ks++) {
            int kb = ks * 64 + t4 * 16;
            const char* ar = wsm + (mb + g) * XROW2 + kb;
            uint4 A0 = *(const uint4*)(ar);              // a0h,a2h,a0l,a2l
            uint4 A1 = *(const uint4*)(ar + 8 * XROW2);  // a1h,a3h,a1l,a3l
#pragma unroll
            for (int nt = 0; nt < 15; nt++) {
                uint4 B = *(const uint4*)(xt + rowb[nt] + dl0 + kb); // b0h,b1h,b0l,b1l
                mma_bf16(acc[nt], A0.x, A1.x, A0.y, A1.y, B.x, B.y); // hi*hi
                mma_bf16(acc[nt], A0.x, A1.x, A0.y, A1.y, B.z, B.w); // hi*lo
                mma_bf16(acc[nt], A0.z, A1.z, A0.w, A1.w, B.x, B.y); // lo*hi
            }
        }
    }

#pragma unroll
    for (int nt = 0; nt < 15; nt++) {
        int pb = (nh * 15 + nt) * 8 + 2 * t4;
        if (pb < NPIX) {
            int o = mb + g;
            float bv = bias[o];
            dst[o * PSTR + pb] = silu(acc[nt][0] + bv);
            if (pb + 1 < NPIX) dst[o * PSTR + pb + 1] = silu(acc[nt][1] + bv);
            float bv2 = bias[o + 8];
            dst[(o + 8) * PSTR + pb] = silu(acc[nt][2] + bv2);
            if (pb + 1 < NPIX) dst[(o + 8) * PSTR + pb + 1] = silu(acc[nt][3] + bv2);
        }
    }
}

// -------- tensor-core pointwise 128->128 + silu; ADD: dst += silu(pw(src)) --------
template <int ADD>
__global__ __launch_bounds__(512, 1) void k_pw_mma(
    const float* __restrict__ srcb, float* __restrict__ dstb,
    const __nv_bfloat16* __restrict__ w,   // [128][272] interleaved
    const float* __restrict__ bias) {
    extern __shared__ char smem[];
    char* xt  = smem;              // XP2
    char* wsm = smem + XP2;        // WT2
    int b = blockIdx.x, d = blockIdx.y;
    int tid = threadIdx.x, lane = tid & 31, wid = tid >> 5;
    const float* src = srcb + (size_t)(d * NB + b) * DM * PSTR;
    float*       dst = dstb + (size_t)(d * NB + b) * DM * PSTR;

    for (int i = tid * 16; i < XP2; i += 512 * 16)
        *(float4*)(xt + i) = make_float4(0.f, 0.f, 0.f, 0.f);
    __syncthreads();
    for (int idx = tid; idx < DM * NPIX; idx += 512) {
        int c = idx / NPIX, p = idx - c * NPIX;
        float v = src[c * PSTR + p];
        __nv_bfloat16 hi = __float2bfloat16(v);
        __nv_bfloat16 lo = __float2bfloat16(v - __bfloat162float(hi));
        int off = p * XROW2 + kbyte(kphys(c));
        *(__nv_bfloat16*)(xt + off)     = hi;
        *(__nv_bfloat16*)(xt + off + 8) = lo;
    }
    {
        const float4* ws = (const float4*)w;
        float4* wd = (float4*)wsm;
        for (int i = tid; i < WT2 / 16; i += 512) wd[i] = ws[i];
    }
    __syncthreads();

    const int g  = lane >> 2;
    const int t4 = lane & 3;
    const int mb = (wid & 7) * 16;
    const int nh = wid >> 3;
    const int pb0 = nh * 128;

    float acc[16][4];
#pragma unroll
    for (int nt = 0; nt < 16; nt++) {
        acc[nt][0] = 0.f; acc[nt][1] = 0.f; acc[nt][2] = 0.f; acc[nt][3] = 0.f;
    }

#pragma unroll
    for (int ks = 0; ks < 8; ks++) {
        int kb = ks * 64 + t4 * 16;
        const char* ar = wsm + (mb + g) * XROW2 + kb;
        uint4 A0 = *(const uint4*)(ar);
        uint4 A1 = *(const uint4*)(ar + 8 * XROW2);
        const char* xr = xt + (pb0 + g) * XROW2 + kb;
#pragma unroll
        for (int nt = 0; nt < 16; nt++) {
            uint4 B = *(const uint4*)(xr + nt * 8 * XROW2);
            mma_bf16(acc[nt], A0.x, A1.x, A0.y, A1.y, B.x, B.y);
            mma_bf16(acc[nt], A0.x, A1.x, A0.y, A1.y, B.z, B.w);
            mma_bf16(acc[nt], A0.z, A1.z, A0.w, A1.w, B.x, B.y);
        }
    }

#pragma unroll
    for (int nt = 0; nt < 16; nt++) {
        int pb = pb0 + nt * 8 + 2 * t4;
        if (pb < NPIX) {
            int o = mb + g;
            float bv = bias[o];
            float* dp = dst + o * PSTR;
            float y0 = silu(acc[nt][0] + bv);
            if (ADD) y0 += dp[pb];
            dp[pb] = y0;
            if (pb + 1 < NPIX) {
                float y1 = silu(acc[nt][1] + bv);
                if (ADD) y1 += dp[pb + 1];
                dp[pb + 1] = y1;
            }
            float bv2 = bias[o + 8];
            float* dq = dst + (o + 8) * PSTR;
            float y2 = silu(acc[nt][2] + bv2);
            if (ADD) y2 += dq[pb];
            dq[pb] = y2;
            if (pb + 1 < NPIX) {
                float y3 = silu(acc[nt][3] + bv2);
                if (ADD) y3 += dq[pb + 1];
                dq[pb + 1] = y3;
            }
        }
    }
}

// -------- fused: fin(128->64) per dir, tanh-clamp, sum dirs, prelu/4, heads --------
__global__ __launch_bounds__(256, 1) void k_fin(
    const float* __restrict__ xsb, const float* __restrict__ wT,
    const float* __restrict__ bias, const float* __restrict__ prelu,
    const float* __restrict__ pdww, const float* __restrict__ pdwb,
    const float* __restrict__ ppw,
    const float* __restrict__ vl1w, const float* __restrict__ vl1b,
    const float* __restrict__ vl2w, const float* __restrict__ vl2b,
    const float* __restrict__ vlfw, const float* __restrict__ vlfb,
    const float* __restrict__ pscale, const float* __restrict__ vscale,
    float* __restrict__ out) {
    extern __shared__ float sm[];
    float* xsm  = sm;
    float* facc = sm + DM * XST;
    __shared__ float vbuf[32], h1[32], h2[32];
    int b = blockIdx.x, tid = threadIdx.x, lane = tid & 31, wid = tid >> 5;

    for (int i = tid; i < DOUT * PADP; i += 256) facc[i] = 0.f;

    for (int d = 0; d < 4; d++) {
        __syncthreads();
        const float* src = xsb + (size_t)(d * NB + b) * DM * PSTR;
        for (int c = wid; c < DM; c += 8) {
            const float* s = src + c * PSTR;
            float* xq = xsm + c * XST;
            for (int p = lane; p < NPIX; p += 32) xq[p] = s[p];
            if (lane < 31) xq[NPIX + lane] = 0.f;
        }
        __syncthreads();

        for (int pass = 0; pass < 2; pass++) {
            int obase = pass * 32 + wid * 4;
            ull acc[4][4];
#pragma unroll
            for (int j = 0; j < 4; j++)
#pragma unroll
                for (int k = 0; k < 4; k++) acc[j][k] = 0ull;

#pragma unroll 4
            for (int i = 0; i < DM; i++) {
                float4 wv = *(const float4*)(wT + i * DOUT + obase);
                ull w0 = pack2(wv.x, wv.x), w1 = pack2(wv.y, wv.y);
                ull w2 = pack2(wv.z, wv.z), w3 = pack2(wv.w, wv.w);
                const ull* xr = (const ull*)(xsm + i * XST) + lane;
#pragma unroll
                for (int k = 0; k < 4; k++) {
                    ull xx = xr[32 * k];
                    acc[0][k] = fma2(xx, w0, acc[0][k]);
                    acc[1][k] = fma2(xx, w1, acc[1][k]);
                    acc[2][k] = fma2(xx, w2, acc[2][k]);
                    acc[3][k] = fma2(xx, w3, acc[3][k]);
                }
            }
#pragma unroll
            for (int j = 0; j < 4; j++) {
                int o = obase + j;
                float bv = bias[o];
                float* fo = facc + o * PADP;
#pragma unroll
                for (int k = 0; k < 4; k++) {
                    int px = 2 * (lane + 32 * k);
                    float2 v = unpack2(acc[j][k]);
                    if (px < NPIX) {
                        int h = px / 15, w = px - h * 15;
                        fo[(h + 1) * 17 + w + 1] += MAXF * tanhf((v.x + bv) * INV_MAXF);
                    }
                    if (px + 1 < NPIX) {
                        int h = (px + 1) / 15, w = (px + 1) - h * 15;
                        fo[(h + 1) * 17 + w + 1] += MAXF * tanhf((v.y + bv) * INV_MAXF);
                    }
                }
            }
        }
    }
    __syncthreads();

    for (int idx = tid; idx < DOUT * NPIX; idx += 256) {
        int o = idx / NPIX, p = idx - o * NPIX;
        int h = p / 15, w = p - h * 15;
        float* fp = &facc[o * PADP + (h + 1) * 17 + w + 1];
        float v = *fp;
        *fp = (v >= 0.f ? v : prelu[o] * v) * 0.25f;
    }
    __syncthreads();

    if (tid < NPIX) {
        int h = tid / 15, w = tid - h * 15;
        int base = (h + 1) * 17 + (w + 1);
        float acc = 0.f;
        for (int c = 0; c < DP; c++) {
            const float* fc = facc + c * PADP + base;
            const float* wk = pdww + c * 9;
            float s = pdwb[c];
#pragma unroll
            for (int r = 0; r < 3; r++)
#pragma unroll
                for (int cc = 0; cc < 3; cc++)
                    s += wk[r * 3 + cc] * fc[(r - 1) * 17 + (cc - 1)];
            s = (s >= 0.f) ? s : s * 0.0625f;
            s = fminf(fmaxf(s, -MAXF), MAXF);
            acc += ppw[c] * s;
        }
        acc = (acc >= 0.f) ? acc : acc * 0.0625f;
        out[NB * 3 + (size_t)b * NPIX + tid] = acc * pscale[0];
    }
    __syncthreads();

    if (wid == 0) {
        const float* fc = facc + (DP + lane) * PADP;
        float s = 0.f;
        for (int h = 0; h < 15; h++)
#pragma unroll
            for (int w = 0; w < 15; w++) s += fc[(h + 1) * 17 + w + 1];
        vbuf[lane] = fmaxf(s * (1.f / 225.f), 0.f);
        __syncwarp();
        float a = vl1b[lane];
        for (int i = 0; i < 32; i++) a += vl1w[lane * 32 + i] * vbuf[i];
        h1[lane] = fminf(fmaxf(a, 0.f), MAXM);
        __syncwarp();
        float g = vl2b[lane];
        for (int i = 0; i < 32; i++) g += vl2w[lane * 32 + i] * h1[i];
        h2[lane] = fminf(fmaxf(g, 0.f), MAXM);
        __syncwarp();
        if (lane < 3) {
            float o = vlfb[lane];
            for (int i = 0; i < 32; i++) o += vlfw[lane * 32 + i] * h2[i];
            out[(size_t)b * 3 + lane] = o * vscale[0];
        }
    }
}

// ---------------- host ----------------
extern "C" void kernel_launch(void* const* d_in, const int* in_sizes, int n_in,
                              void* d_out, int out_size) {
    const float* x       = (const float*)d_in[0];
    const float* map_w   = (const float*)d_in[1];
    const float* map_b   = (const float*)d_in[2];
    const float* dconv_w = (const float*)d_in[3];
    const float* dconv_b = (const float*)d_in[4];
    const float* c1_w    = (const float*)d_in[5];
    const float* c1_b    = (const float*)d_in[6];
    const float* r0_w1   = (const float*)d_in[7];
    const float* r0_b1   = (const float*)d_in[8];
    const float* r0_w2   = (const float*)d_in[9];
    const float* r0_b2   = (const float*)d_in[10];
    const float* fin_w   = (const float*)d_in[11];
    const float* fin_b   = (const float*)d_in[12];
    const float* prelu_w = (const float*)d_in[13];
    const float* pdw_w   = (const float*)d_in[14];
    const float* pdw_b   = (const float*)d_in[15];
    const float* ppw_w   = (const float*)d_in[16];
    const float* vl1_w   = (const float*)d_in[17];
    const float* vl1_b   = (const float*)d_in[18];
    const float* vl2_w   = (const float*)d_in[19];
    const float* vl2_b   = (const float*)d_in[20];
    const float* vlf_w   = (const float*)d_in[21];
    const float* vlf_b   = (const float*)d_in[22];
    const float* pscale  = (const float*)d_in[23];
    const float* vscale  = (const float*)d_in[24];
    float* out = (float*)d_out;

    float *xs, *tmp, *wfn;
    __nv_bfloat16 *w;
    cudaGetSymbolAddress((void**)&xs,  g_xs);
    cudaGetSymbolAddress((void**)&tmp, g_tmp);
    cudaGetSymbolAddress((void**)&w,   g_w);
    cudaGetSymbolAddress((void**)&wfn, g_wfn);

    cudaFuncSetAttribute(k_dirconv_mma, cudaFuncAttributeMaxDynamicSharedMemorySize, SMD2);
    cudaFuncSetAttribute(k_pw_mma<0>, cudaFuncAttributeMaxDynamicSharedMemorySize, SMP2);
    cudaFuncSetAttribute(k_pw_mma<1>, cudaFuncAttributeMaxDynamicSharedMemorySize, SMP2);
    cudaFuncSetAttribute(k_fin, cudaFuncAttributeMaxDynamicSharedMemorySize, SMC);

    const int MS = 128 * 272;   // bf16 elements per prepped matrix

    k_prep<<<256, 256>>>(dconv_w, c1_w, r0_w1, r0_w2, w);
    k_xpose_fin<<<32, 256>>>(fin_w, wfn);

    dim3 gbd(NB, 4);
    k_map<<<gbd, 256>>>(x, map_w, map_b, xs);
    for (int l = 0; l < 4; l++) {
        k_dirconv_mma<<<gbd, 512, SMD2>>>(xs, tmp, w + (size_t)l * 3 * MS,
                                          dconv_b + l * DM);
        k_pw_mma<1><<<gbd, 512, SMP2>>>(tmp, xs, w + (size_t)(12 + l) * MS,
                                        c1_b + l * DM);
    }
    k_pw_mma<0><<<gbd, 512, SMP2>>>(xs, tmp, w + (size_t)16 * MS, r0_b1);
    k_pw_mma<1><<<gbd, 512, SMP2>>>(tmp, xs, w + (size_t)17 * MS, r0_b2);

    k_fin<<<NB, 256, SMC>>>(xs, wfn, fin_b, prelu_w, pdw_w, pdw_b, ppw_w,
                            vl1_w, vl1_b, vl2_w, vl2_b, vlf_w, vlf_b,
                            pscale, vscale, out);
}

// round 14
// speedup vs baseline: 1.1983x; 1.1983x over previous
#include <cuda_runtime.h>
#include <cuda_bf16.h>
#include <math.h>

typedef unsigned long long ull;
typedef unsigned int uint;

#define NB   512
#define DM   128
#define DOUT 64
#define DP   32
#define NPIX 225
#define PSTR 228
#define PADP 292
#define XST  256
#define MAXF 31.75f
#define INV_MAXF (1.0f/31.75f)
#define MAXM (127.0f/3.515625f)

// mma smem layout constants (R11 proven layout)
#define XROWB 272                      // bytes per x^T row (136 bf16)
#define XROWS 289                      // padded 17x17 pixels (dirconv)
#define XT_BYTES (XROWS*XROWB)         // 78608
#define WROWB 272
#define WT_BYTES (128*WROWB)           // 34816
#define SMD (2*XT_BYTES + 2*WT_BYTES)  // 226848  (dirconv)

#define XP_BYTES (256*XROWB)           // 69632   (pw dense 256-px tile)
#define SMP (2*XP_BYTES + 2*WT_BYTES)  // 208896  (pw)

#define WT64_BYTES (64*WROWB)          // 17408   (fin 64-row weight tile)
#define SMF (2*XP_BYTES + 2*WT64_BYTES)// 174080  (fin64)
#define SMH (DOUT*PADP*4)              // 74752   (heads)

// ---------------- device scratch ----------------
__device__ __align__(16) float g_xs [4ull*NB*DM*PSTR];
__device__ __align__(16) float g_tmp[4ull*NB*DM*PSTR];
// 19 weight matrices, bf16 hi/lo [19][128][136]:
//  0..11 dconv l*3+t, 12..15 c1 l, 16 r0_w1, 17 r0_w2, 18 fin (rows 0..63)
__device__ __align__(16) __nv_bfloat16 g_wh[19*128*136];
__device__ __align__(16) __nv_bfloat16 g_wl[19*128*136];

__constant__ int c_dr[4][3] = {{0,0,0},{-1,0,1},{-1,0,1},{1,0,-1}};
__constant__ int c_dc[4][3] = {{-1,0,1},{0,0,0},{-1,0,1},{-1,0,1}};

// ---------------- helpers ----------------
__device__ __forceinline__ float silu(float x) {
    return __fdividef(x, 1.f + __expf(-x));
}
__device__ __forceinline__ void mma_bf16(float* c,
    uint a0, uint a1, uint a2, uint a3, uint b0, uint b1) {
    asm("mma.sync.aligned.m16n8k16.row.col.f32.bf16.bf16.f32 "
        "{%0,%1,%2,%3}, {%4,%5,%6,%7}, {%8,%9}, {%0,%1,%2,%3};"
        : "+f"(c[0]), "+f"(c[1]), "+f"(c[2]), "+f"(c[3])
        : "r"(a0), "r"(a1), "r"(a2), "r"(a3), "r"(b0), "r"(b1));
}

// ---------------- weight prep: 19x f32 [o][128] -> bf16 hi/lo [o][136] ----------------
__global__ void k_prep(const float* __restrict__ dconv,
                       const float* __restrict__ c1,
                       const float* __restrict__ r1,
                       const float* __restrict__ r2,
                       const float* __restrict__ fin,
                       __nv_bfloat16* __restrict__ wh,
                       __nv_bfloat16* __restrict__ wl) {
    int n = 19 * 128 * 136;
    for (int idx = blockIdx.x * blockDim.x + threadIdx.x; idx < n;
         idx += gridDim.x * blockDim.x) {
        int m = idx / (128 * 136);
        int rem = idx - m * 128 * 136;
        int o = rem / 136, i = rem - o * 136;
        float v = 0.f;
        if (i < 128) {
            if (m < 12)       v = dconv[(m * 128 + o) * 128 + i];
            else if (m < 16)  v = c1[((m - 12) * 128 + o) * 128 + i];
            else if (m == 16) v = r1[o * 128 + i];
            else if (m == 17) v = r2[o * 128 + i];
            else if (o < 64)  v = fin[o * 128 + i];
        }
        __nv_bfloat16 hi = __float2bfloat16(v);
        wh[idx] = hi;
        wl[idx] = __float2bfloat16(v - __bfloat162float(hi));
    }
}

// ---------------- input map conv (2 -> 128) + silu ----------------
__global__ __launch_bounds__(256) void k_map(const float* __restrict__ x,
                                             const float* __restrict__ mw,
                                             const float* __restrict__ mb,
                                             float* __restrict__ xsb) {
    int b = blockIdx.x, d = blockIdx.y, tid = threadIdx.x;
    __shared__ float xp[2 * PADP];
    for (int i = tid; i < 2 * PADP; i += 256) xp[i] = 0.f;
    __syncthreads();
    const float* xb = x + (size_t)b * 2 * NPIX;
    for (int i = tid; i < 2 * NPIX; i += 256) {
        int c = i / NPIX, p = i - c * NPIX;
        int h = p / 15, w = p - h * 15;
        xp[c * PADP + (h + 1) * 17 + (w + 1)] = xb[i];
    }
    __syncthreads();
    int dr[3], dc[3];
#pragma unroll
    for (int t = 0; t < 3; t++) { dr[t] = c_dr[d][t]; dc[t] = c_dc[d][t]; }
    float* dst = xsb + (size_t)(d * NB + b) * DM * PSTR;
    for (int idx = tid; idx < DM * NPIX; idx += 256) {
        int o = idx / NPIX, p = idx - o * NPIX;
        int h = p / 15, w = p - h * 15;
        float acc = mb[o];
#pragma unroll
        for (int t = 0; t < 3; t++) {
            int off = (h + 1 + dr[t]) * 17 + (w + 1 + dc[t]);
            acc += mw[(t * DM + o) * 2 + 0] * xp[off]
                 + mw[(t * DM + o) * 2 + 1] * xp[PADP + off];
        }
        dst[o * PSTR + p] = silu(acc);
    }
}

// -------- tensor-core directional 3-tap conv 128->128 + silu (R10/R11 proven) --------
__global__ __launch_bounds__(512, 1) void k_dirconv_mma(
    const float* __restrict__ srcb, float* __restrict__ dstb,
    const __nv_bfloat16* __restrict__ wh,   // [3][128][136]
    const __nv_bfloat16* __restrict__ wl,
    const float* __restrict__ bias) {
    extern __shared__ char smem[];
    char* xh  = smem;
    char* xl  = smem + XT_BYTES;
    char* wsh = smem + 2 * XT_BYTES;
    char* wsl = wsh + WT_BYTES;
    int b = blockIdx.x, d = blockIdx.y;
    int tid = threadIdx.x, lane = tid & 31, wid = tid >> 5;
    const float* src = srcb + (size_t)(d * NB + b) * DM * PSTR;
    float*       dst = dstb + (size_t)(d * NB + b) * DM * PSTR;

    for (int i = tid * 16; i < 2 * XT_BYTES; i += 512 * 16)
        *(float4*)(smem + i) = make_float4(0.f, 0.f, 0.f, 0.f);
    __syncthreads();
    for (int idx = tid; idx < DM * NPIX; idx += 512) {
        int c = idx / NPIX, p = idx - c * NPIX;
        int h = p / 15, w = p - h * 15;
        int rp = (h + 1) * 17 + (w + 1);
        float v = src[c * PSTR + p];
        __nv_bfloat16 hi = __float2bfloat16(v);
        __nv_bfloat16 lo = __float2bfloat16(v - __bfloat162float(hi));
        *(__nv_bfloat16*)(xh + rp * XROWB + c * 2) = hi;
        *(__nv_bfloat16*)(xl + rp * XROWB + c * 2) = lo;
    }

    const int g  = lane >> 2;
    const int t4 = lane & 3;
    const int mb = (wid & 7) * 16;
    const int nh = wid >> 3;

    int rowb[15];
#pragma unroll
    for (int nt = 0; nt < 15; nt++) {
        int p = (nh * 15 + nt) * 8 + g;
        int pc = (p < NPIX) ? p : (NPIX - 1);
        int h = pc / 15, w = pc - h * 15;
        rowb[nt] = ((h + 1) * 17 + (w + 1)) * XROWB;
    }

    float acc[15][4];
#pragma unroll
    for (int nt = 0; nt < 15; nt++) {
        acc[nt][0] = 0.f; acc[nt][1] = 0.f; acc[nt][2] = 0.f; acc[nt][3] = 0.f;
    }

    int dlt[3];
#pragma unroll
    for (int t = 0; t < 3; t++) dlt[t] = (c_dr[d][t] * 17 + c_dc[d][t]) * XROWB;

    for (int tp = 0; tp < 3; tp++) {
        __syncthreads();
        {
            const float4* sh = (const float4*)(wh + tp * 128 * 136);
            const float4* sl = (const float4*)(wl + tp * 128 * 136);
            float4* dh = (float4*)wsh;
            float4* dl = (float4*)wsl;
            for (int i = tid; i < WT_BYTES / 16; i += 512) { dh[i] = sh[i]; dl[i] = sl[i]; }
        }
        __syncthreads();
        const int dl0 = dlt[tp];

#pragma unroll
        for (int ks = 0; ks < 8; ks++) {
            int kb = ks * 32 + t4 * 4;
            const char* ah = wsh + (mb + g) * WROWB + kb;
            uint a0h = *(const uint*)(ah);
            uint a1h = *(const uint*)(ah + 8 * WROWB);
            uint a2h = *(const uint*)(ah + 16);
            uint a3h = *(const uint*)(ah + 8 * WROWB + 16);
            const char* al = wsl + (mb + g) * WROWB + kb;
            uint a0l = *(const uint*)(al);
            uint a1l = *(const uint*)(al + 8 * WROWB);
            uint a2l = *(const uint*)(al + 16);
            uint a3l = *(const uint*)(al + 8 * WROWB + 16);
#pragma unroll
            for (int nt = 0; nt < 15; nt++) {
                const char* bp = xh + (rowb[nt] + dl0 + kb);
                uint b0h = *(const uint*)(bp);
                uint b1h = *(const uint*)(bp + 16);
                const char* bq = xl + (rowb[nt] + dl0 + kb);
                uint b0l = *(const uint*)(bq);
                uint b1l = *(const uint*)(bq + 16);
                mma_bf16(acc[nt], a0h, a1h, a2h, a3h, b0h, b1h);
                mma_bf16(acc[nt], a0h, a1h, a2h, a3h, b0l, b1l);
                mma_bf16(acc[nt], a0l, a1l, a2l, a3l, b0h, b1h);
            }
        }
    }

#pragma unroll
    for (int nt = 0; nt < 15; nt++) {
        int pb = (nh * 15 + nt) * 8 + 2 * t4;
        if (pb < NPIX) {
            int o = mb + g;
            float bv = bias[o];
            dst[o * PSTR + pb] = silu(acc[nt][0] + bv);
            if (pb + 1 < NPIX) dst[o * PSTR + pb + 1] = silu(acc[nt][1] + bv);
            float bv2 = bias[o + 8];
            dst[(o + 8) * PSTR + pb] = silu(acc[nt][2] + bv2);
            if (pb + 1 < NPIX) dst[(o + 8) * PSTR + pb + 1] = silu(acc[nt][3] + bv2);
        }
    }
}

// -------- tensor-core pointwise 128->128 + silu; ADD: dst += silu(pw(src)) (R11 proven) --------
template <int ADD>
__global__ __launch_bounds__(512, 1) void k_pw_mma(
    const float* __restrict__ srcb, float* __restrict__ dstb,
    const __nv_bfloat16* __restrict__ wh,   // [128][136]
    const __nv_bfloat16* __restrict__ wl,
    const float* __restrict__ bias) {
    extern __shared__ char smem[];
    char* xh  = smem;
    char* xl  = smem + XP_BYTES;
    char* wsh = smem + 2 * XP_BYTES;
    char* wsl = wsh + WT_BYTES;
    int b = blockIdx.x, d = blockIdx.y;
    int tid = threadIdx.x, lane = tid & 31, wid = tid >> 5;
    const float* src = srcb + (size_t)(d * NB + b) * DM * PSTR;
    float*       dst = dstb + (size_t)(d * NB + b) * DM * PSTR;

    for (int i = tid * 16; i < 2 * XP_BYTES; i += 512 * 16)
        *(float4*)(smem + i) = make_float4(0.f, 0.f, 0.f, 0.f);
    __syncthreads();
    for (int idx = tid; idx < DM * NPIX; idx += 512) {
        int c = idx / NPIX, p = idx - c * NPIX;
        float v = src[c * PSTR + p];
        __nv_bfloat16 hi = __float2bfloat16(v);
        __nv_bfloat16 lo = __float2bfloat16(v - __bfloat162float(hi));
        *(__nv_bfloat16*)(xh + p * XROWB + c * 2) = hi;
        *(__nv_bfloat16*)(xl + p * XROWB + c * 2) = lo;
    }
    {
        const float4* sh = (const float4*)wh;
        const float4* sl = (const float4*)wl;
        float4* dh = (float4*)wsh;
        float4* dl = (float4*)wsl;
        for (int i = tid; i < WT_BYTES / 16; i += 512) { dh[i] = sh[i]; dl[i] = sl[i]; }
    }
    __syncthreads();

    const int g  = lane >> 2;
    const int t4 = lane & 3;
    const int mb = (wid & 7) * 16;
    const int nh = wid >> 3;
    const int pb0 = nh * 128;

    float acc[16][4];
#pragma unroll
    for (int nt = 0; nt < 16; nt++) {
        acc[nt][0] = 0.f; acc[nt][1] = 0.f; acc[nt][2] = 0.f; acc[nt][3] = 0.f;
    }

#pragma unroll
    for (int ks = 0; ks < 8; ks++) {
        int kb = ks * 32 + t4 * 4;
        const char* ah = wsh + (mb + g) * WROWB + kb;
        uint a0h = *(const uint*)(ah);
        uint a1h = *(const uint*)(ah + 8 * WROWB);
        uint a2h = *(const uint*)(ah + 16);
        uint a3h = *(const uint*)(ah + 8 * WROWB + 16);
        const char* al = wsl + (mb + g) * WROWB + kb;
        uint a0l = *(const uint*)(al);
        uint a1l = *(const uint*)(al + 8 * WROWB);
        uint a2l = *(const uint*)(al + 16);
        uint a3l = *(const uint*)(al + 8 * WROWB + 16);
        const char* xrh = xh + (pb0 + g) * XROWB + kb;
        const char* xrl = xl + (pb0 + g) * XROWB + kb;
#pragma unroll
        for (int nt = 0; nt < 16; nt++) {
            const char* bp = xrh + nt * 8 * XROWB;
            uint b0h = *(const uint*)(bp);
            uint b1h = *(const uint*)(bp + 16);
            const char* bq = xrl + nt * 8 * XROWB;
            uint b0l = *(const uint*)(bq);
            uint b1l = *(const uint*)(bq + 16);
            mma_bf16(acc[nt], a0h, a1h, a2h, a3h, b0h, b1h);
            mma_bf16(acc[nt], a0h, a1h, a2h, a3h, b0l, b1l);
            mma_bf16(acc[nt], a0l, a1l, a2l, a3l, b0h, b1h);
        }
    }

#pragma unroll
    for (int nt = 0; nt < 16; nt++) {
        int pb = pb0 + nt * 8 + 2 * t4;
        if (pb < NPIX) {
            int o = mb + g;
            float bv = bias[o];
            float* dp = dst + o * PSTR;
            float y0 = silu(acc[nt][0] + bv);
            if (ADD) y0 += dp[pb];
            dp[pb] = y0;
            if (pb + 1 < NPIX) {
                float y1 = silu(acc[nt][1] + bv);
                if (ADD) y1 += dp[pb + 1];
                dp[pb + 1] = y1;
            }
            float bv2 = bias[o + 8];
            float* dq = dst + (o + 8) * PSTR;
            float y2 = silu(acc[nt][2] + bv2);
            if (ADD) y2 += dq[pb];
            dq[pb] = y2;
            if (pb + 1 < NPIX) {
                float y3 = silu(acc[nt][3] + bv2);
                if (ADD) y3 += dq[pb + 1];
                dq[pb + 1] = y3;
            }
        }
    }
}

// -------- tensor-core fin conv 128->64, linear epilogue (acc+bias, no activation) --------
// Warp = (m-tile wid&3 -> 16 o, pixel-quarter wid>>2 -> 8 n-tiles of 8 px).
__global__ __launch_bounds__(512, 1) void k_fin64(
    const float* __restrict__ srcb, float* __restrict__ dstb,
    const __nv_bfloat16* __restrict__ wh,   // rows 0..63 valid
    const __nv_bfloat16* __restrict__ wl,
    const float* __restrict__ bias) {
    extern __shared__ char smem[];
    char* xh  = smem;
    char* xl  = smem + XP_BYTES;
    char* wsh = smem + 2 * XP_BYTES;
    char* wsl = wsh + WT64_BYTES;
    int b = blockIdx.x, d = blockIdx.y;
    int tid = threadIdx.x, lane = tid & 31, wid = tid >> 5;
    const float* src = srcb + (size_t)(d * NB + b) * DM * PSTR;
    float*       dst = dstb + (size_t)(d * NB + b) * DOUT * PSTR;

    for (int i = tid * 16; i < 2 * XP_BYTES; i += 512 * 16)
        *(float4*)(smem + i) = make_float4(0.f, 0.f, 0.f, 0.f);
    __syncthreads();
    for (int idx = tid; idx < DM * NPIX; idx += 512) {
        int c = idx / NPIX, p = idx - c * NPIX;
        float v = src[c * PSTR + p];
        __nv_bfloat16 hi = __float2bfloat16(v);
        __nv_bfloat16 lo = __float2bfloat16(v - __bfloat162float(hi));
        *(__nv_bfloat16*)(xh + p * XROWB + c * 2) = hi;
        *(__nv_bfloat16*)(xl + p * XROWB + c * 2) = lo;
    }
    {
        const float4* sh = (const float4*)wh;
        const float4* sl = (const float4*)wl;
        float4* dh = (float4*)wsh;
        float4* dl = (float4*)wsl;
        for (int i = tid; i < WT64_BYTES / 16; i += 512) { dh[i] = sh[i]; dl[i] = sl[i]; }
    }
    __syncthreads();

    const int g  = lane >> 2;
    const int t4 = lane & 3;
    const int mb = (wid & 3) * 16;
    const int nh = wid >> 2;            // 0..3
    const int pb0 = nh * 64;

    float acc[8][4];
#pragma unroll
    for (int nt = 0; nt < 8; nt++) {
        acc[nt][0] = 0.f; acc[nt][1] = 0.f; acc[nt][2] = 0.f; acc[nt][3] = 0.f;
    }

#pragma unroll
    for (int ks = 0; ks < 8; ks++) {
        int kb = ks * 32 + t4 * 4;
        const char* ah = wsh + (mb + g) * WROWB + kb;
        uint a0h = *(const uint*)(ah);
        uint a1h = *(const uint*)(ah + 8 * WROWB);
        uint a2h = *(const uint*)(ah + 16);
        uint a3h = *(const uint*)(ah + 8 * WROWB + 16);
        const char* al = wsl + (mb + g) * WROWB + kb;
        uint a0l = *(const uint*)(al);
        uint a1l = *(const uint*)(al + 8 * WROWB);
        uint a2l = *(const uint*)(al + 16);
        uint a3l = *(const uint*)(al + 8 * WROWB + 16);
        const char* xrh = xh + (pb0 + g) * XROWB + kb;
        const char* xrl = xl + (pb0 + g) * XROWB + kb;
#pragma unroll
        for (int nt = 0; nt < 8; nt++) {
            const char* bp = xrh + nt * 8 * XROWB;
            uint b0h = *(const uint*)(bp);
            uint b1h = *(const uint*)(bp + 16);
            const char* bq = xrl + nt * 8 * XROWB;
            uint b0l = *(const uint*)(bq);
            uint b1l = *(const uint*)(bq + 16);
            mma_bf16(acc[nt], a0h, a1h, a2h, a3h, b0h, b1h);
            mma_bf16(acc[nt], a0h, a1h, a2h, a3h, b0l, b1l);
            mma_bf16(acc[nt], a0l, a1l, a2l, a3l, b0h, b1h);
        }
    }

#pragma unroll
    for (int nt = 0; nt < 8; nt++) {
        int pb = pb0 + nt * 8 + 2 * t4;
        if (pb < NPIX) {
            int o = mb + g;
            float bv = bias[o];
            float* dp = dst + o * PSTR;
            dp[pb] = acc[nt][0] + bv;
            if (pb + 1 < NPIX) dp[pb + 1] = acc[nt][1] + bv;
            float bv2 = bias[o + 8];
            float* dq = dst + (o + 8) * PSTR;
            dq[pb] = acc[nt][2] + bv2;
            if (pb + 1 < NPIX) dq[pb + 1] = acc[nt][3] + bv2;
        }
    }
}

// -------- heads: tanh-clamp + sum dirs + prelu/4, then policy + value --------
__global__ __launch_bounds__(256, 1) void k_heads(
    const float* __restrict__ finb,   // [4][NB][DOUT][PSTR]
    const float* __restrict__ prelu,
    const float* __restrict__ pdww, const float* __restrict__ pdwb,
    const float* __restrict__ ppw,
    const float* __restrict__ vl1w, const float* __restrict__ vl1b,
    const float* __restrict__ vl2w, const float* __restrict__ vl2b,
    const float* __restrict__ vlfw, const float* __restrict__ vlfb,
    const float* __restrict__ pscale, const float* __restrict__ vscale,
    float* __restrict__ out) {
    extern __shared__ float facc[];   // DOUT*PADP
    __shared__ float vbuf[32], h1[32], h2[32];
    int b = blockIdx.x, tid = threadIdx.x, lane = tid & 31, wid = tid >> 5;

    for (int i = tid; i < DOUT * PADP; i += 256) facc[i] = 0.f;
    __syncthreads();

    for (int idx = tid; idx < DOUT * NPIX; idx += 256) {
        int o = idx / NPIX, p = idx - o * NPIX;
        float s = 0.f;
#pragma unroll
        for (int d = 0; d < 4; d++) {
            float v = finb[((size_t)(d * NB + b) * DOUT + o) * PSTR + p];
            s += MAXF * tanhf(v * INV_MAXF);
        }
        s = (s >= 0.f ? s : prelu[o] * s) * 0.25f;
        int h = p / 15, w = p - h * 15;
        facc[o * PADP + (h + 1) * 17 + w + 1] = s;
    }
    __syncthreads();

    // policy head
    if (tid < NPIX) {
        int h = tid / 15, w = tid - h * 15;
        int base = (h + 1) * 17 + (w + 1);
        float acc = 0.f;
        for (int c = 0; c < DP; c++) {
            const float* fc = facc + c * PADP + base;
            const float* wk = pdww + c * 9;
            float s = pdwb[c];
#pragma unroll
            for (int r = 0; r < 3; r++)
#pragma unroll
                for (int cc = 0; cc < 3; cc++)
                    s += wk[r * 3 + cc] * fc[(r - 1) * 17 + (cc - 1)];
            s = (s >= 0.f) ? s : s * 0.0625f;
            s = fminf(fmaxf(s, -MAXF), MAXF);
            acc += ppw[c] * s;
        }
        acc = (acc >= 0.f) ? acc : acc * 0.0625f;
        out[NB * 3 + (size_t)b * NPIX + tid] = acc * pscale[0];
    }
    __syncthreads();

    // value head (warp 0)
    if (wid == 0) {
        const float* fc = facc + (DP + lane) * PADP;
        float s = 0.f;
        for (int h = 0; h < 15; h++)
#pragma unroll
            for (int w = 0; w < 15; w++) s += fc[(h + 1) * 17 + w + 1];
        vbuf[lane] = fmaxf(s * (1.f / 225.f), 0.f);
        __syncwarp();
        float a = vl1b[lane];
        for (int i = 0; i < 32; i++) a += vl1w[lane * 32 + i] * vbuf[i];
        h1[lane] = fminf(fmaxf(a, 0.f), MAXM);
        __syncwarp();
        float g = vl2b[lane];
        for (int i = 0; i < 32; i++) g += vl2w[lane * 32 + i] * h1[i];
        h2[lane] = fminf(fmaxf(g, 0.f), MAXM);
        __syncwarp();
        if (lane < 3) {
            float o = vlfb[lane];
            for (int i = 0; i < 32; i++) o += vlfw[lane * 32 + i] * h2[i];
            out[(size_t)b * 3 + lane] = o * vscale[0];
        }
    }
}

// ---------------- host ----------------
extern "C" void kernel_launch(void* const* d_in, const int* in_sizes, int n_in,
                              void* d_out, int out_size) {
    const float* x       = (const float*)d_in[0];
    const float* map_w   = (const float*)d_in[1];
    const float* map_b   = (const float*)d_in[2];
    const float* dconv_w = (const float*)d_in[3];
    const float* dconv_b = (const float*)d_in[4];
    const float* c1_w    = (const float*)d_in[5];
    const float* c1_b    = (const float*)d_in[6];
    const float* r0_w1   = (const float*)d_in[7];
    const float* r0_b1   = (const float*)d_in[8];
    const float* r0_w2   = (const float*)d_in[9];
    const float* r0_b2   = (const float*)d_in[10];
    const float* fin_w   = (const float*)d_in[11];
    const float* fin_b   = (const float*)d_in[12];
    const float* prelu_w = (const float*)d_in[13];
    const float* pdw_w   = (const float*)d_in[14];
    const float* pdw_b   = (const float*)d_in[15];
    const float* ppw_w   = (const float*)d_in[16];
    const float* vl1_w   = (const float*)d_in[17];
    const float* vl1_b   = (const float*)d_in[18];
    const float* vl2_w   = (const float*)d_in[19];
    const float* vl2_b   = (const float*)d_in[20];
    const float* vlf_w   = (const float*)d_in[21];
    const float* vlf_b   = (const float*)d_in[22];
    const float* pscale  = (const float*)d_in[23];
    const float* vscale  = (const float*)d_in[24];
    float* out = (float*)d_out;

    float *xs, *tmp;
    __nv_bfloat16 *wh, *wl;
    cudaGetSymbolAddress((void**)&xs,  g_xs);
    cudaGetSymbolAddress((void**)&tmp, g_tmp);
    cudaGetSymbolAddress((void**)&wh,  g_wh);
    cudaGetSymbolAddress((void**)&wl,  g_wl);

    cudaFuncSetAttribute(k_dirconv_mma, cudaFuncAttributeMaxDynamicSharedMemorySize, SMD);
    cudaFuncSetAttribute(k_pw_mma<0>, cudaFuncAttributeMaxDynamicSharedMemorySize, SMP);
    cudaFuncSetAttribute(k_pw_mma<1>, cudaFuncAttributeMaxDynamicSharedMemorySize, SMP);
    cudaFuncSetAttribute(k_fin64, cudaFuncAttributeMaxDynamicSharedMemorySize, SMF);
    cudaFuncSetAttribute(k_heads, cudaFuncAttributeMaxDynamicSharedMemorySize, SMH);

    const int MS = 128 * 136;   // elements per prepped matrix

    // launches 1-2 (keep ncu -s 5 -c 1 on a dirconv)
    k_prep<<<256, 256>>>(dconv_w, c1_w, r0_w1, r0_w2, fin_w, wh, wl);
    k_map<<<dim3(NB, 4), 256>>>(x, map_w, map_b, xs);

    dim3 gbd(NB, 4);
    for (int l = 0; l < 4; l++) {
        k_dirconv_mma<<<gbd, 512, SMD>>>(xs, tmp, wh + l * 3 * MS,
                                         wl + l * 3 * MS, dconv_b + l * DM);
        k_pw_mma<1><<<gbd, 512, SMP>>>(tmp, xs, wh + (12 + l) * MS,
                                       wl + (12 + l) * MS, c1_b + l * DM);
    }
    k_pw_mma<0><<<gbd, 512, SMP>>>(xs, tmp, wh + 16 * MS, wl + 16 * MS, r0_b1);
    k_pw_mma<1><<<gbd, 512, SMP>>>(tmp, xs, wh + 17 * MS, wl + 17 * MS, r0_b2);

    // fin conv (linear) into tmp, then heads
    k_fin64<<<gbd, 512, SMF>>>(xs, tmp, wh + 18 * MS, wl + 18 * MS, fin_b);
    k_heads<<<NB, 256, SMH>>>(tmp, prelu_w, pdw_w, pdw_b, ppw_w,
                              vl1_w, vl1_b, vl2_w, vl2_b, vlf_w, vlf_b,
                              pscale, vscale, out);
}

// round 15
// speedup vs baseline: 1.5340x; 1.2801x over previous
#include <cuda_runtime.h>
#include <cuda_bf16.h>
#include <math.h>

typedef unsigned long long ull;
typedef unsigned int uint;

#define NB   512
#define DM   128
#define DOUT 64
#define DP   32
#define NPIX 225
#define PSTR 228
#define PADP 292
#define MAXF 31.75f
#define INV_MAXF (1.0f/31.75f)
#define MAXM (127.0f/3.515625f)

// mma smem layout constants (R11/R13 proven layout)
#define XROWB 272                      // bytes per x^T row (136 bf16)
#define XT_BYTES (289*XROWB)           // dirconv padded 17x17 tile: 78608
#define WROWB 272
#define WT_BYTES (128*WROWB)           // 34816
#define SMD (2*XT_BYTES + 2*WT_BYTES)  // 226848  (k_layer)

#define XP_BYTES (256*XROWB)           // 69632   (dense 256-px tile)
#define SMP (2*XP_BYTES + 2*WT_BYTES)  // 208896  (k_res)

#define WT64_BYTES (64*WROWB)          // 17408
#define SMF (2*XP_BYTES + 2*WT64_BYTES)// 174080  (fin64)
#define SMH (DOUT*PADP*4)              // 74752   (heads)

// ---------------- device scratch ----------------
__device__ __align__(16) float g_xs [4ull*NB*DM*PSTR];
__device__ __align__(16) float g_tmp[4ull*NB*DM*PSTR];
// 19 weight matrices, bf16 hi/lo [19][128][136]:
//  0..11 dconv l*3+t, 12..15 c1 l, 16 r0_w1, 17 r0_w2, 18 fin (rows 0..63)
__device__ __align__(16) __nv_bfloat16 g_wh[19*128*136];
__device__ __align__(16) __nv_bfloat16 g_wl[19*128*136];

__constant__ int c_dr[4][3] = {{0,0,0},{-1,0,1},{-1,0,1},{1,0,-1}};
__constant__ int c_dc[4][3] = {{-1,0,1},{0,0,0},{-1,0,1},{-1,0,1}};

// ---------------- helpers ----------------
__device__ __forceinline__ float silu(float x) {
    return __fdividef(x, 1.f + __expf(-x));
}
__device__ __forceinline__ void mma_bf16(float* c,
    uint a0, uint a1, uint a2, uint a3, uint b0, uint b1) {
    asm("mma.sync.aligned.m16n8k16.row.col.f32.bf16.bf16.f32 "
        "{%0,%1,%2,%3}, {%4,%5,%6,%7}, {%8,%9}, {%0,%1,%2,%3};"
        : "+f"(c[0]), "+f"(c[1]), "+f"(c[2]), "+f"(c[3])
        : "r"(a0), "r"(a1), "r"(a2), "r"(a3), "r"(b0), "r"(b1));
}
__device__ __forceinline__ void split_store(char* th, char* tl, int off, float y) {
    __nv_bfloat16 hi = __float2bfloat16(y);
    __nv_bfloat16 lo = __float2bfloat16(y - __bfloat162float(hi));
    *(__nv_bfloat16*)(th + off) = hi;
    *(__nv_bfloat16*)(tl + off) = lo;
}

// ---------------- weight prep: 19x f32 [o][128] -> bf16 hi/lo [o][136] ----------------
__global__ void k_prep(const float* __restrict__ dconv,
                       const float* __restrict__ c1,
                       const float* __restrict__ r1,
                       const float* __restrict__ r2,
                       const float* __restrict__ fin,
                       __nv_bfloat16* __restrict__ wh,
                       __nv_bfloat16* __restrict__ wl) {
    int n = 19 * 128 * 136;
    for (int idx = blockIdx.x * blockDim.x + threadIdx.x; idx < n;
         idx += gridDim.x * blockDim.x) {
        int m = idx / (128 * 136);
        int rem = idx - m * 128 * 136;
        int o = rem / 136, i = rem - o * 136;
        float v = 0.f;
        if (i < 128) {
            if (m < 12)       v = dconv[(m * 128 + o) * 128 + i];
            else if (m < 16)  v = c1[((m - 12) * 128 + o) * 128 + i];
            else if (m == 16) v = r1[o * 128 + i];
            else if (m == 17) v = r2[o * 128 + i];
            else if (o < 64)  v = fin[o * 128 + i];
        }
        __nv_bfloat16 hi = __float2bfloat16(v);
        wh[idx] = hi;
        wl[idx] = __float2bfloat16(v - __bfloat162float(hi));
    }
}

// ---------------- input map conv (2 -> 128) + silu ----------------
__global__ __launch_bounds__(256) void k_map(const float* __restrict__ x,
                                             const float* __restrict__ mw,
                                             const float* __restrict__ mb,
                                             float* __restrict__ xsb) {
    int b = blockIdx.x, d = blockIdx.y, tid = threadIdx.x;
    __shared__ float xp[2 * PADP];
    for (int i = tid; i < 2 * PADP; i += 256) xp[i] = 0.f;
    __syncthreads();
    const float* xb = x + (size_t)b * 2 * NPIX;
    for (int i = tid; i < 2 * NPIX; i += 256) {
        int c = i / NPIX, p = i - c * NPIX;
        int h = p / 15, w = p - h * 15;
        xp[c * PADP + (h + 1) * 17 + (w + 1)] = xb[i];
    }
    __syncthreads();
    int dr[3], dc[3];
#pragma unroll
    for (int t = 0; t < 3; t++) { dr[t] = c_dr[d][t]; dc[t] = c_dc[d][t]; }
    float* dst = xsb + (size_t)(d * NB + b) * DM * PSTR;
    for (int idx = tid; idx < DM * NPIX; idx += 256) {
        int o = idx / NPIX, p = idx - o * NPIX;
        int h = p / 15, w = p - h * 15;
        float acc = mb[o];
#pragma unroll
        for (int t = 0; t < 3; t++) {
            int off = (h + 1 + dr[t]) * 17 + (w + 1 + dc[t]);
            acc += mw[(t * DM + o) * 2 + 0] * xp[off]
                 + mw[(t * DM + o) * 2 + 1] * xp[PADP + off];
        }
        dst[o * PSTR + p] = silu(acc);
    }
}

// ======== fused layer: xs = xs + silu(c1 @ silu(dirconv(xs))) ========
// Phase A = proven dirconv mma mainloop; epilogue writes bf16 hi/lo dense
// tiles into smem (overlaying dead padded tiles). Phase B = proven pw mma
// mainloop; epilogue adds residual into xs.
__global__ __launch_bounds__(512, 1) void k_layer(
    float* __restrict__ xsb,
    const __nv_bfloat16* __restrict__ whdc,  // [3][128][136]
    const __nv_bfloat16* __restrict__ wldc,
    const float* __restrict__ bdc,
    const __nv_bfloat16* __restrict__ whc1,  // [128][136]
    const __nv_bfloat16* __restrict__ wlc1,
    const float* __restrict__ bc1) {
    extern __shared__ char smem[];
    char* xh  = smem;                 // phase A: padded hi tile
    char* xl  = smem + XT_BYTES;      // phase A: padded lo tile
    char* wsh = smem + 2 * XT_BYTES;
    char* wsl = wsh + WT_BYTES;
    int b = blockIdx.x, d = blockIdx.y;
    int tid = threadIdx.x, lane = tid & 31, wid = tid >> 5;
    float* xsg = xsb + (size_t)(d * NB + b) * DM * PSTR;

    for (int i = tid * 16; i < 2 * XT_BYTES; i += 512 * 16)
        *(float4*)(smem + i) = make_float4(0.f, 0.f, 0.f, 0.f);
    __syncthreads();
    for (int idx = tid; idx < DM * NPIX; idx += 512) {
        int c = idx / NPIX, p = idx - c * NPIX;
        int h = p / 15, w = p - h * 15;
        int rp = (h + 1) * 17 + (w + 1);
        float v = xsg[c * PSTR + p];
        split_store(xh, xl, rp * XROWB + c * 2, v);
    }

    const int g  = lane >> 2;
    const int t4 = lane & 3;
    const int mb = (wid & 7) * 16;
    const int nh = wid >> 3;

    // ---- phase A: dirconv ----
    int rowb[15];
#pragma unroll
    for (int nt = 0; nt < 15; nt++) {
        int p = (nh * 15 + nt) * 8 + g;
        int pc = (p < NPIX) ? p : (NPIX - 1);
        int h = pc / 15, w = pc - h * 15;
        rowb[nt] = ((h + 1) * 17 + (w + 1)) * XROWB;
    }

    float acc[15][4];
#pragma unroll
    for (int nt = 0; nt < 15; nt++) {
        acc[nt][0] = 0.f; acc[nt][1] = 0.f; acc[nt][2] = 0.f; acc[nt][3] = 0.f;
    }

    int dlt[3];
#pragma unroll
    for (int t = 0; t < 3; t++) dlt[t] = (c_dr[d][t] * 17 + c_dc[d][t]) * XROWB;

    for (int tp = 0; tp < 3; tp++) {
        __syncthreads();
        {
            const float4* sh = (const float4*)(whdc + tp * 128 * 136);
            const float4* sl = (const float4*)(wldc + tp * 128 * 136);
            float4* dh = (float4*)wsh;
            float4* dl = (float4*)wsl;
            for (int i = tid; i < WT_BYTES / 16; i += 512) { dh[i] = sh[i]; dl[i] = sl[i]; }
        }
        __syncthreads();
        const int dl0 = dlt[tp];

#pragma unroll
        for (int ks = 0; ks < 8; ks++) {
            int kb = ks * 32 + t4 * 4;
            const char* ah = wsh + (mb + g) * WROWB + kb;
            uint a0h = *(const uint*)(ah);
            uint a1h = *(const uint*)(ah + 8 * WROWB);
            uint a2h = *(const uint*)(ah + 16);
            uint a3h = *(const uint*)(ah + 8 * WROWB + 16);
            const char* al = wsl + (mb + g) * WROWB + kb;
            uint a0l = *(const uint*)(al);
            uint a1l = *(const uint*)(al + 8 * WROWB);
            uint a2l = *(const uint*)(al + 16);
            uint a3l = *(const uint*)(al + 8 * WROWB + 16);
#pragma unroll
            for (int nt = 0; nt < 15; nt++) {
                const char* bp = xh + (rowb[nt] + dl0 + kb);
                uint b0h = *(const uint*)(bp);
                uint b1h = *(const uint*)(bp + 16);
                const char* bq = xl + (rowb[nt] + dl0 + kb);
                uint b0l = *(const uint*)(bq);
                uint b1l = *(const uint*)(bq + 16);
                mma_bf16(acc[nt], a0h, a1h, a2h, a3h, b0h, b1h);
                mma_bf16(acc[nt], a0h, a1h, a2h, a3h, b0l, b1l);
                mma_bf16(acc[nt], a0l, a1l, a2l, a3l, b0h, b1h);
            }
        }
    }

    __syncthreads();   // all phase-A reads of tiles + weights complete

    // ---- phase A epilogue: silu -> dense bf16 hi/lo tiles (overlay) ----
    char* dxh = smem;                 // dense [256 px][136 ch] hi
    char* dxl = smem + XP_BYTES;      // dense lo
#pragma unroll
    for (int nt = 0; nt < 15; nt++) {
        int pb = (nh * 15 + nt) * 8 + 2 * t4;
        if (pb < NPIX) {
            int o = mb + g;
            float bv = bdc[o], bv2 = bdc[o + 8];
            // pb+1 <= 225 is in-bounds of the 256-row tile; row 225 is junk-tolerant
            split_store(dxh, dxl, pb * XROWB + o * 2,           silu(acc[nt][0] + bv));
            split_store(dxh, dxl, (pb + 1) * XROWB + o * 2,     silu(acc[nt][1] + bv));
            split_store(dxh, dxl, pb * XROWB + (o + 8) * 2,     silu(acc[nt][2] + bv2));
            split_store(dxh, dxl, (pb + 1) * XROWB + (o + 8) * 2, silu(acc[nt][3] + bv2));
        }
    }
    {   // stage c1 weights into the freed weight region
        const float4* sh = (const float4*)whc1;
        const float4* sl = (const float4*)wlc1;
        float4* dh = (float4*)wsh;
        float4* dl = (float4*)wsl;
        for (int i = tid; i < WT_BYTES / 16; i += 512) { dh[i] = sh[i]; dl[i] = sl[i]; }
    }
    __syncthreads();

    // ---- phase B: pointwise c1 ----
    const int pb0 = nh * 128;
    float acc2[16][4];
#pragma unroll
    for (int nt = 0; nt < 16; nt++) {
        acc2[nt][0] = 0.f; acc2[nt][1] = 0.f; acc2[nt][2] = 0.f; acc2[nt][3] = 0.f;
    }

#pragma unroll
    for (int ks = 0; ks < 8; ks++) {
        int kb = ks * 32 + t4 * 4;
        const char* ah = wsh + (mb + g) * WROWB + kb;
        uint a0h = *(const uint*)(ah);
        uint a1h = *(const uint*)(ah + 8 * WROWB);
        uint a2h = *(const uint*)(ah + 16);
        uint a3h = *(const uint*)(ah + 8 * WROWB + 16);
        const char* al = wsl + (mb + g) * WROWB + kb;
        uint a0l = *(const uint*)(al);
        uint a1l = *(const uint*)(al + 8 * WROWB);
        uint a2l = *(const uint*)(al + 16);
        uint a3l = *(const uint*)(al + 8 * WROWB + 16);
        const char* xrh = dxh + (pb0 + g) * XROWB + kb;
        const char* xrl = dxl + (pb0 + g) * XROWB + kb;
#pragma unroll
        for (int nt = 0; nt < 16; nt++) {
            const char* bp = xrh + nt * 8 * XROWB;
            uint b0h = *(const uint*)(bp);
            uint b1h = *(const uint*)(bp + 16);
            const char* bq = xrl + nt * 8 * XROWB;
            uint b0l = *(const uint*)(bq);
            uint b1l = *(const uint*)(bq + 16);
            mma_bf16(acc2[nt], a0h, a1h, a2h, a3h, b0h, b1h);
            mma_bf16(acc2[nt], a0h, a1h, a2h, a3h, b0l, b1l);
            mma_bf16(acc2[nt], a0l, a1l, a2l, a3l, b0h, b1h);
        }
    }

    // ---- phase B epilogue: residual add into xs ----
#pragma unroll
    for (int nt = 0; nt < 16; nt++) {
        int pb = pb0 + nt * 8 + 2 * t4;
        if (pb < NPIX) {
            int o = mb + g;
            float bv = bc1[o];
            float* dp = xsg + o * PSTR;
            dp[pb] = silu(acc2[nt][0] + bv) + dp[pb];
            if (pb + 1 < NPIX) dp[pb + 1] = silu(acc2[nt][1] + bv) + dp[pb + 1];
            float bv2 = bc1[o + 8];
            float* dq = xsg + (o + 8) * PSTR;
            dq[pb] = silu(acc2[nt][2] + bv2) + dq[pb];
            if (pb + 1 < NPIX) dq[pb + 1] = silu(acc2[nt][3] + bv2) + dq[pb + 1];
        }
    }
}

// ======== fused residual block: xs = xs + silu(w2 @ silu(w1 @ xs)) ========
__global__ __launch_bounds__(512, 1) void k_res(
    float* __restrict__ xsb,
    const __nv_bfloat16* __restrict__ wh1, const __nv_bfloat16* __restrict__ wl1,
    const float* __restrict__ b1v,
    const __nv_bfloat16* __restrict__ wh2, const __nv_bfloat16* __restrict__ wl2,
    const float* __restrict__ b2v) {
    extern __shared__ char smem[];
    char* dxh = smem;
    char* dxl = smem + XP_BYTES;
    char* wsh = smem + 2 * XP_BYTES;
    char* wsl = wsh + WT_BYTES;
    int b = blockIdx.x, d = blockIdx.y;
    int tid = threadIdx.x, lane = tid & 31, wid = tid >> 5;
    float* xsg = xsb + (size_t)(d * NB + b) * DM * PSTR;

    for (int i = tid * 16; i < 2 * XP_BYTES; i += 512 * 16)
        *(float4*)(smem + i) = make_float4(0.f, 0.f, 0.f, 0.f);
    __syncthreads();
    for (int idx = tid; idx < DM * NPIX; idx += 512) {
        int c = idx / NPIX, p = idx - c * NPIX;
        split_store(dxh, dxl, p * XROWB + c * 2, xsg[c * PSTR + p]);
    }
    {
        const float4* sh = (const float4*)wh1;
        const float4* sl = (const float4*)wl1;
        float4* dh = (float4*)wsh;
        float4* dl = (float4*)wsl;
        for (int i = tid; i < WT_BYTES / 16; i += 512) { dh[i] = sh[i]; dl[i] = sl[i]; }
    }
    __syncthreads();

    const int g  = lane >> 2;
    const int t4 = lane & 3;
    const int mb = (wid & 7) * 16;
    const int nh = wid >> 3;
    const int pb0 = nh * 128;

    float acc[16][4];
#pragma unroll
    for (int nt = 0; nt < 16; nt++) {
        acc[nt][0] = 0.f; acc[nt][1] = 0.f; acc[nt][2] = 0.f; acc[nt][3] = 0.f;
    }

#pragma unroll
    for (int ks = 0; ks < 8; ks++) {
        int kb = ks * 32 + t4 * 4;
        const char* ah = wsh + (mb + g) * WROWB + kb;
        uint a0h = *(const uint*)(ah);
        uint a1h = *(const uint*)(ah + 8 * WROWB);
        uint a2h = *(const uint*)(ah + 16);
        uint a3h = *(const uint*)(ah + 8 * WROWB + 16);
        const char* al = wsl + (mb + g) * WROWB + kb;
        uint a0l = *(const uint*)(al);
        uint a1l = *(const uint*)(al + 8 * WROWB);
        uint a2l = *(const uint*)(al + 16);
        uint a3l = *(const uint*)(al + 8 * WROWB + 16);
        const char* xrh = dxh + (pb0 + g) * XROWB + kb;
        const char* xrl = dxl + (pb0 + g) * XROWB + kb;
#pragma unroll
        for (int nt = 0; nt < 16; nt++) {
            const char* bp = xrh + nt * 8 * XROWB;
            uint b0h = *(const uint*)(bp);
            uint b1h = *(const uint*)(bp + 16);
            const char* bq = xrl + nt * 8 * XROWB;
            uint b0l = *(const uint*)(bq);
            uint b1l = *(const uint*)(bq + 16);
            mma_bf16(acc[nt], a0h, a1h, a2h, a3h, b0h, b1h);
            mma_bf16(acc[nt], a0h, a1h, a2h, a3h, b0l, b1l);
            mma_bf16(acc[nt], a0l, a1l, a2l, a3l, b0h, b1h);
        }
    }

    __syncthreads();   // mainloop1 reads complete

    // epilogue1: silu -> overwrite the same tiles (rows >=225 stay zero)
#pragma unroll
    for (int nt = 0; nt < 16; nt++) {
        int pb = pb0 + nt * 8 + 2 * t4;
        if (pb < NPIX) {
            int o = mb + g;
            float bv = b1v[o], bv2 = b1v[o + 8];
            split_store(dxh, dxl, pb * XROWB + o * 2,             silu(acc[nt][0] + bv));
            if (pb + 1 < NPIX)
                split_store(dxh, dxl, (pb + 1) * XROWB + o * 2,   silu(acc[nt][1] + bv));
            split_store(dxh, dxl, pb * XROWB + (o + 8) * 2,       silu(acc[nt][2] + bv2));
            if (pb + 1 < NPIX)
                split_store(dxh, dxl, (pb + 1) * XROWB + (o + 8) * 2, silu(acc[nt][3] + bv2));
        }
    }
    {
        const float4* sh = (const float4*)wh2;
        const float4* sl = (const float4*)wl2;
        float4* dh = (float4*)wsh;
        float4* dl = (float4*)wsl;
        for (int i = tid; i < WT_BYTES / 16; i += 512) { dh[i] = sh[i]; dl[i] = sl[i]; }
    }
    __syncthreads();

    float acc2[16][4];
#pragma unroll
    for (int nt = 0; nt < 16; nt++) {
        acc2[nt][0] = 0.f; acc2[nt][1] = 0.f; acc2[nt][2] = 0.f; acc2[nt][3] = 0.f;
    }

#pragma unroll
    for (int ks = 0; ks < 8; ks++) {
        int kb = ks * 32 + t4 * 4;
        const char* ah = wsh + (mb + g) * WROWB + kb;
        uint a0h = *(const uint*)(ah);
        uint a1h = *(const uint*)(ah + 8 * WROWB);
        uint a2h = *(const uint*)(ah + 16);
        uint a3h = *(const uint*)(ah + 8 * WROWB + 16);
        const char* al = wsl + (mb + g) * WROWB + kb;
        uint a0l = *(const uint*)(al);
        uint a1l = *(const uint*)(al + 8 * WROWB);
        uint a2l = *(const uint*)(al + 16);
        uint a3l = *(const uint*)(al + 8 * WROWB + 16);
        const char* xrh = dxh + (pb0 + g) * XROWB + kb;
        const char* xrl = dxl + (pb0 + g) * XROWB + kb;
#pragma unroll
        for (int nt = 0; nt < 16; nt++) {
            const char* bp = xrh + nt * 8 * XROWB;
            uint b0h = *(const uint*)(bp);
            uint b1h = *(const uint*)(bp + 16);
            const char* bq = xrl + nt * 8 * XROWB;
            uint b0l = *(const uint*)(bq);
            uint b1l = *(const uint*)(bq + 16);
            mma_bf16(acc2[nt], a0h, a1h, a2h, a3h, b0h, b1h);
            mma_bf16(acc2[nt], a0h, a1h, a2h, a3h, b0l, b1l);
            mma_bf16(acc2[nt], a0l, a1l, a2l, a3l, b0h, b1h);
        }
    }

#pragma unroll
    for (int nt = 0; nt < 16; nt++) {
        int pb = pb0 + nt * 8 + 2 * t4;
        if (pb < NPIX) {
            int o = mb + g;
            float bv = b2v[o];
            float* dp = xsg + o * PSTR;
            dp[pb] = silu(acc2[nt][0] + bv) + dp[pb];
            if (pb + 1 < NPIX) dp[pb + 1] = silu(acc2[nt][1] + bv) + dp[pb + 1];
            float bv2 = b2v[o + 8];
            float* dq = xsg + (o + 8) * PSTR;
            dq[pb] = silu(acc2[nt][2] + bv2) + dq[pb];
            if (pb + 1 < NPIX) dq[pb + 1] = silu(acc2[nt][3] + bv2) + dq[pb + 1];
        }
    }
}

// -------- tensor-core fin conv 128->64, linear epilogue (R13 proven) --------
__global__ __launch_bounds__(512, 1) void k_fin64(
    const float* __restrict__ srcb, float* __restrict__ dstb,
    const __nv_bfloat16* __restrict__ wh,   // rows 0..63 valid
    const __nv_bfloat16* __restrict__ wl,
    const float* __restrict__ bias) {
    extern __shared__ char smem[];
    char* xh  = smem;
    char* xl  = smem + XP_BYTES;
    char* wsh = smem + 2 * XP_BYTES;
    char* wsl = wsh + WT64_BYTES;
    int b = blockIdx.x, d = blockIdx.y;
    int tid = threadIdx.x, lane = tid & 31, wid = tid >> 5;
    const float* src = srcb + (size_t)(d * NB + b) * DM * PSTR;
    float*       dst = dstb + (size_t)(d * NB + b) * DOUT * PSTR;

    for (int i = tid * 16; i < 2 * XP_BYTES; i += 512 * 16)
        *(float4*)(smem + i) = make_float4(0.f, 0.f, 0.f, 0.f);
    __syncthreads();
    for (int idx = tid; idx < DM * NPIX; idx += 512) {
        int c = idx / NPIX, p = idx - c * NPIX;
        split_store(xh, xl, p * XROWB + c * 2, src[c * PSTR + p]);
    }
    {
        const float4* sh = (const float4*)wh;
        const float4* sl = (const float4*)wl;
        float4* dh = (float4*)wsh;
        float4* dl = (float4*)wsl;
        for (int i = tid; i < WT64_BYTES / 16; i += 512) { dh[i] = sh[i]; dl[i] = sl[i]; }
    }
    __syncthreads();

    const int g  = lane >> 2;
    const int t4 = lane & 3;
    const int mb = (wid & 3) * 16;
    const int nh = wid >> 2;
    const int pb0 = nh * 64;

    float acc[8][4];
#pragma unroll
    for (int nt = 0; nt < 8; nt++) {
        acc[nt][0] = 0.f; acc[nt][1] = 0.f; acc[nt][2] = 0.f; acc[nt][3] = 0.f;
    }

#pragma unroll
    for (int ks = 0; ks < 8; ks++) {
        int kb = ks * 32 + t4 * 4;
        const char* ah = wsh + (mb + g) * WROWB + kb;
        uint a0h = *(const uint*)(ah);
        uint a1h = *(const uint*)(ah + 8 * WROWB);
        uint a2h = *(const uint*)(ah + 16);
        uint a3h = *(const uint*)(ah + 8 * WROWB + 16);
        const char* al = wsl + (mb + g) * WROWB + kb;
        uint a0l = *(const uint*)(al);
        uint a1l = *(const uint*)(al + 8 * WROWB);
        uint a2l = *(const uint*)(al + 16);
        uint a3l = *(const uint*)(al + 8 * WROWB + 16);
        const char* xrh = xh + (pb0 + g) * XROWB + kb;
        const char* xrl = xl + (pb0 + g) * XROWB + kb;
#pragma unroll
        for (int nt = 0; nt < 8; nt++) {
            const char* bp = xrh + nt * 8 * XROWB;
            uint b0h = *(const uint*)(bp);
            uint b1h = *(const uint*)(bp + 16);
            const char* bq = xrl + nt * 8 * XROWB;
            uint b0l = *(const uint*)(bq);
            uint b1l = *(const uint*)(bq + 16);
            mma_bf16(acc[nt], a0h, a1h, a2h, a3h, b0h, b1h);
            mma_bf16(acc[nt], a0h, a1h, a2h, a3h, b0l, b1l);
            mma_bf16(acc[nt], a0l, a1l, a2l, a3l, b0h, b1h);
        }
    }

#pragma unroll
    for (int nt = 0; nt < 8; nt++) {
        int pb = pb0 + nt * 8 + 2 * t4;
        if (pb < NPIX) {
            int o = mb + g;
            float bv = bias[o];
            float* dp = dst + o * PSTR;
            dp[pb] = acc[nt][0] + bv;
            if (pb + 1 < NPIX) dp[pb + 1] = acc[nt][1] + bv;
            float bv2 = bias[o + 8];
            float* dq = dst + (o + 8) * PSTR;
            dq[pb] = acc[nt][2] + bv2;
            if (pb + 1 < NPIX) dq[pb + 1] = acc[nt][3] + bv2;
        }
    }
}

// -------- heads: tanh-clamp + sum dirs + prelu/4, then policy + value (R13 proven) --------
__global__ __launch_bounds__(256, 1) void k_heads(
    const float* __restrict__ finb,   // [4][NB][DOUT][PSTR]
    const float* __restrict__ prelu,
    const float* __restrict__ pdww, const float* __restrict__ pdwb,
    const float* __restrict__ ppw,
    const float* __restrict__ vl1w, const float* __restrict__ vl1b,
    const float* __restrict__ vl2w, const float* __restrict__ vl2b,
    const float* __restrict__ vlfw, const float* __restrict__ vlfb,
    const float* __restrict__ pscale, const float* __restrict__ vscale,
    float* __restrict__ out) {
    extern __shared__ float facc[];   // DOUT*PADP
    __shared__ float vbuf[32], h1[32], h2[32];
    int b = blockIdx.x, tid = threadIdx.x, lane = tid & 31, wid = tid >> 5;

    for (int i = tid; i < DOUT * PADP; i += 256) facc[i] = 0.f;
    __syncthreads();

    for (int idx = tid; idx < DOUT * NPIX; idx += 256) {
        int o = idx / NPIX, p = idx - o * NPIX;
        float s = 0.f;
#pragma unroll
        for (int d = 0; d < 4; d++) {
            float v = finb[((size_t)(d * NB + b) * DOUT + o) * PSTR + p];
            s += MAXF * tanhf(v * INV_MAXF);
        }
        s = (s >= 0.f ? s : prelu[o] * s) * 0.25f;
        int h = p / 15, w = p - h * 15;
        facc[o * PADP + (h + 1) * 17 + w + 1] = s;
    }
    __syncthreads();

    if (tid < NPIX) {
        int h = tid / 15, w = tid - h * 15;
        int base = (h + 1) * 17 + (w + 1);
        float acc = 0.f;
        for (int c = 0; c < DP; c++) {
            const float* fc = facc + c * PADP + base;
            const float* wk = pdww + c * 9;
            float s = pdwb[c];
#pragma unroll
            for (int r = 0; r < 3; r++)
#pragma unroll
                for (int cc = 0; cc < 3; cc++)
                    s += wk[r * 3 + cc] * fc[(r - 1) * 17 + (cc - 1)];
            s = (s >= 0.f) ? s : s * 0.0625f;
            s = fminf(fmaxf(s, -MAXF), MAXF);
            acc += ppw[c] * s;
        }
        acc = (acc >= 0.f) ? acc : acc * 0.0625f;
        out[NB * 3 + (size_t)b * NPIX + tid] = acc * pscale[0];
    }
    __syncthreads();

    if (wid == 0) {
        const float* fc = facc + (DP + lane) * PADP;
        float s = 0.f;
        for (int h = 0; h < 15; h++)
#pragma unroll
            for (int w = 0; w < 15; w++) s += fc[(h + 1) * 17 + w + 1];
        vbuf[lane] = fmaxf(s * (1.f / 225.f), 0.f);
        __syncwarp();
        float a = vl1b[lane];
        for (int i = 0; i < 32; i++) a += vl1w[lane * 32 + i] * vbuf[i];
        h1[lane] = fminf(fmaxf(a, 0.f), MAXM);
        __syncwarp();
        float g = vl2b[lane];
        for (int i = 0; i < 32; i++) g += vl2w[lane * 32 + i] * h1[i];
        h2[lane] = fminf(fmaxf(g, 0.f), MAXM);
        __syncwarp();
        if (lane < 3) {
            float o = vlfb[lane];
            for (int i = 0; i < 32; i++) o += vlfw[lane * 32 + i] * h2[i];
            out[(size_t)b * 3 + lane] = o * vscale[0];
        }
    }
}

// ---------------- host ----------------
extern "C" void kernel_launch(void* const* d_in, const int* in_sizes, int n_in,
                              void* d_out, int out_size) {
    const float* x       = (const float*)d_in[0];
    const float* map_w   = (const float*)d_in[1];
    const float* map_b   = (const float*)d_in[2];
    const float* dconv_w = (const float*)d_in[3];
    const float* dconv_b = (const float*)d_in[4];
    const float* c1_w    = (const float*)d_in[5];
    const float* c1_b    = (const float*)d_in[6];
    const float* r0_w1   = (const float*)d_in[7];
    const float* r0_b1   = (const float*)d_in[8];
    const float* r0_w2   = (const float*)d_in[9];
    const float* r0_b2   = (const float*)d_in[10];
    const float* fin_w   = (const float*)d_in[11];
    const float* fin_b   = (const float*)d_in[12];
    const float* prelu_w = (const float*)d_in[13];
    const float* pdw_w   = (const float*)d_in[14];
    const float* pdw_b   = (const float*)d_in[15];
    const float* ppw_w   = (const float*)d_in[16];
    const float* vl1_w   = (const float*)d_in[17];
    const float* vl1_b   = (const float*)d_in[18];
    const float* vl2_w   = (const float*)d_in[19];
    const float* vl2_b   = (const float*)d_in[20];
    const float* vlf_w   = (const float*)d_in[21];
    const float* vlf_b   = (const float*)d_in[22];
    const float* pscale  = (const float*)d_in[23];
    const float* vscale  = (const float*)d_in[24];
    float* out = (float*)d_out;

    float *xs, *tmp;
    __nv_bfloat16 *wh, *wl;
    cudaGetSymbolAddress((void**)&xs,  g_xs);
    cudaGetSymbolAddress((void**)&tmp, g_tmp);
    cudaGetSymbolAddress((void**)&wh,  g_wh);
    cudaGetSymbolAddress((void**)&wl,  g_wl);

    cudaFuncSetAttribute(k_layer, cudaFuncAttributeMaxDynamicSharedMemorySize, SMD);
    cudaFuncSetAttribute(k_res,   cudaFuncAttributeMaxDynamicSharedMemorySize, SMP);
    cudaFuncSetAttribute(k_fin64, cudaFuncAttributeMaxDynamicSharedMemorySize, SMF);
    cudaFuncSetAttribute(k_heads, cudaFuncAttributeMaxDynamicSharedMemorySize, SMH);

    const int MS = 128 * 136;   // elements per prepped matrix

    k_prep<<<256, 256>>>(dconv_w, c1_w, r0_w1, r0_w2, fin_w, wh, wl);   // 1
    k_map<<<dim3(NB, 4), 256>>>(x, map_w, map_b, xs);                   // 2

    dim3 gbd(NB, 4);
    for (int l = 0; l < 4; l++)                                         // 3-6
        k_layer<<<gbd, 512, SMD>>>(xs, wh + l * 3 * MS, wl + l * 3 * MS,
                                   dconv_b + l * DM,
                                   wh + (12 + l) * MS, wl + (12 + l) * MS,
                                   c1_b + l * DM);
    k_res<<<gbd, 512, SMP>>>(xs, wh + 16 * MS, wl + 16 * MS, r0_b1,     // 7
                             wh + 17 * MS, wl + 17 * MS, r0_b2);

    k_fin64<<<gbd, 512, SMF>>>(xs, tmp, wh + 18 * MS, wl + 18 * MS, fin_b); // 8
    k_heads<<<NB, 256, SMH>>>(tmp, prelu_w, pdw_w, pdw_b, ppw_w,            // 9
                              vl1_w, vl1_b, vl2_w, vl2_b, vlf_w, vlf_b,
                              pscale, vscale, out);
}

// round 16
// speedup vs baseline: 1.5365x; 1.0016x over previous
#include <cuda_runtime.h>
#include <cuda_bf16.h>
#include <math.h>

typedef unsigned long long ull;
typedef unsigned int uint;

#define NB   512
#define DM   128
#define DOUT 64
#define DP   32
#define NPIX 225
#define PSTR 228
#define PADP 292
#define MAXF 31.75f
#define INV_MAXF (1.0f/31.75f)
#define MAXM (127.0f/3.515625f)

#define XROWB 272                      // bytes per x^T row (136 bf16)
#define XT_BYTES (289*XROWB)           // dirconv padded 17x17 tile: 78608
#define WROWB 272
#define WT_BYTES (128*WROWB)           // 34816
#define SMD (2*XT_BYTES + 2*WT_BYTES)  // 226848  (k_layer)

#define XP_BYTES (256*XROWB)           // 69632   (dense 256-px tile)
#define SMP (2*XP_BYTES + 2*WT_BYTES)  // 208896  (k_res)

#define WT64_BYTES (64*WROWB)          // 17408
#define SMF (2*XP_BYTES + 2*WT64_BYTES)// 174080  (fin64)
#define SMH (DOUT*PADP*4)              // 74752   (heads)

#define NT3 768                        // threads for k_layer / k_res

// ---------------- device scratch ----------------
__device__ __align__(16) float g_xs [4ull*NB*DM*PSTR];
__device__ __align__(16) float g_tmp[4ull*NB*DM*PSTR];
// 19 weight matrices, bf16 hi/lo [19][128][136]
__device__ __align__(16) __nv_bfloat16 g_wh[19*128*136];
__device__ __align__(16) __nv_bfloat16 g_wl[19*128*136];

__constant__ int c_dr[4][3] = {{0,0,0},{-1,0,1},{-1,0,1},{1,0,-1}};
__constant__ int c_dc[4][3] = {{-1,0,1},{0,0,0},{-1,0,1},{-1,0,1}};

// ---------------- helpers ----------------
__device__ __forceinline__ float silu(float x) {
    return __fdividef(x, 1.f + __expf(-x));
}
__device__ __forceinline__ void mma_bf16(float* c,
    uint a0, uint a1, uint a2, uint a3, uint b0, uint b1) {
    asm("mma.sync.aligned.m16n8k16.row.col.f32.bf16.bf16.f32 "
        "{%0,%1,%2,%3}, {%4,%5,%6,%7}, {%8,%9}, {%0,%1,%2,%3};"
        : "+f"(c[0]), "+f"(c[1]), "+f"(c[2]), "+f"(c[3])
        : "r"(a0), "r"(a1), "r"(a2), "r"(a3), "r"(b0), "r"(b1));
}
__device__ __forceinline__ void split_store(char* th, char* tl, int off, float y) {
    __nv_bfloat16 hi = __float2bfloat16(y);
    __nv_bfloat16 lo = __float2bfloat16(y - __bfloat162float(hi));
    *(__nv_bfloat16*)(th + off) = hi;
    *(__nv_bfloat16*)(tl + off) = lo;
}

// ---------------- weight prep: 19x f32 [o][128] -> bf16 hi/lo [o][136] ----------------
__global__ void k_prep(const float* __restrict__ dconv,
                       const float* __restrict__ c1,
                       const float* __restrict__ r1,
                       const float* __restrict__ r2,
                       const float* __restrict__ fin,
                       __nv_bfloat16* __restrict__ wh,
                       __nv_bfloat16* __restrict__ wl) {
    int n = 19 * 128 * 136;
    for (int idx = blockIdx.x * blockDim.x + threadIdx.x; idx < n;
         idx += gridDim.x * blockDim.x) {
        int m = idx / (128 * 136);
        int rem = idx - m * 128 * 136;
        int o = rem / 136, i = rem - o * 136;
        float v = 0.f;
        if (i < 128) {
            if (m < 12)       v = dconv[(m * 128 + o) * 128 + i];
            else if (m < 16)  v = c1[((m - 12) * 128 + o) * 128 + i];
            else if (m == 16) v = r1[o * 128 + i];
            else if (m == 17) v = r2[o * 128 + i];
            else if (o < 64)  v = fin[o * 128 + i];
        }
        __nv_bfloat16 hi = __float2bfloat16(v);
        wh[idx] = hi;
        wl[idx] = __float2bfloat16(v - __bfloat162float(hi));
    }
}

// ---------------- input map conv (2 -> 128) + silu ----------------
__global__ __launch_bounds__(256) void k_map(const float* __restrict__ x,
                                             const float* __restrict__ mw,
                                             const float* __restrict__ mb,
                                             float* __restrict__ xsb) {
    int b = blockIdx.x, d = blockIdx.y, tid = threadIdx.x;
    __shared__ float xp[2 * PADP];
    for (int i = tid; i < 2 * PADP; i += 256) xp[i] = 0.f;
    __syncthreads();
    const float* xb = x + (size_t)b * 2 * NPIX;
    for (int i = tid; i < 2 * NPIX; i += 256) {
        int c = i / NPIX, p = i - c * NPIX;
        int h = p / 15, w = p - h * 15;
        xp[c * PADP + (h + 1) * 17 + (w + 1)] = xb[i];
    }
    __syncthreads();
    int dr[3], dc[3];
#pragma unroll
    for (int t = 0; t < 3; t++) { dr[t] = c_dr[d][t]; dc[t] = c_dc[d][t]; }
    float* dst = xsb + (size_t)(d * NB + b) * DM * PSTR;
    for (int idx = tid; idx < DM * NPIX; idx += 256) {
        int o = idx / NPIX, p = idx - o * NPIX;
        int h = p / 15, w = p - h * 15;
        float acc = mb[o];
#pragma unroll
        for (int t = 0; t < 3; t++) {
            int off = (h + 1 + dr[t]) * 17 + (w + 1 + dc[t]);
            acc += mw[(t * DM + o) * 2 + 0] * xp[off]
                 + mw[(t * DM + o) * 2 + 1] * xp[PADP + off];
        }
        dst[o * PSTR + p] = silu(acc);
    }
}

// ======== fused layer (768 thr / 24 warps): xs += silu(c1 @ silu(dirconv(xs))) ========
// Warp = (m-tile wid%8 -> 16 o-channels, n-group wid/8 -> 10 pixel-tiles of 8 px).
__global__ __launch_bounds__(NT3, 1) void k_layer(
    float* __restrict__ xsb,
    const __nv_bfloat16* __restrict__ whdc,  // [3][128][136]
    const __nv_bfloat16* __restrict__ wldc,
    const float* __restrict__ bdc,
    const __nv_bfloat16* __restrict__ whc1,  // [128][136]
    const __nv_bfloat16* __restrict__ wlc1,
    const float* __restrict__ bc1) {
    extern __shared__ char smem[];
    char* xh  = smem;                 // phase A: padded hi tile
    char* xl  = smem + XT_BYTES;      // phase A: padded lo tile
    char* wsh = smem + 2 * XT_BYTES;
    char* wsl = wsh + WT_BYTES;
    int b = blockIdx.x, d = blockIdx.y;
    int tid = threadIdx.x, lane = tid & 31, wid = tid >> 5;
    float* xsg = xsb + (size_t)(d * NB + b) * DM * PSTR;

    for (int i = tid * 16; i < 2 * XT_BYTES; i += NT3 * 16)
        *(float4*)(smem + i) = make_float4(0.f, 0.f, 0.f, 0.f);
    __syncthreads();
    for (int idx = tid; idx < DM * NPIX; idx += NT3) {
        int c = idx / NPIX, p = idx - c * NPIX;
        int h = p / 15, w = p - h * 15;
        int rp = (h + 1) * 17 + (w + 1);
        split_store(xh, xl, rp * XROWB + c * 2, xsg[c * PSTR + p]);
    }

    const int g  = lane >> 2;
    const int t4 = lane & 3;
    const int mb = (wid & 7) * 16;      // wid%8
    const int nh = wid >> 3;            // 0..2

    // ---- phase A: dirconv ----
    int rowb[10];
#pragma unroll
    for (int nt = 0; nt < 10; nt++) {
        int p = (nh * 10 + nt) * 8 + g;
        int pc = (p < NPIX) ? p : (NPIX - 1);
        int h = pc / 15, w = pc - h * 15;
        rowb[nt] = ((h + 1) * 17 + (w + 1)) * XROWB;
    }

    float acc[10][4];
#pragma unroll
    for (int nt = 0; nt < 10; nt++) {
        acc[nt][0] = 0.f; acc[nt][1] = 0.f; acc[nt][2] = 0.f; acc[nt][3] = 0.f;
    }

    int dlt[3];
#pragma unroll
    for (int t = 0; t < 3; t++) dlt[t] = (c_dr[d][t] * 17 + c_dc[d][t]) * XROWB;

    for (int tp = 0; tp < 3; tp++) {
        __syncthreads();
        {
            const float4* sh = (const float4*)(whdc + tp * 128 * 136);
            const float4* sl = (const float4*)(wldc + tp * 128 * 136);
            float4* dh = (float4*)wsh;
            float4* dl = (float4*)wsl;
            for (int i = tid; i < WT_BYTES / 16; i += NT3) { dh[i] = sh[i]; dl[i] = sl[i]; }
        }
        __syncthreads();
        const int dl0 = dlt[tp];

#pragma unroll
        for (int ks = 0; ks < 8; ks++) {
            int kb = ks * 32 + t4 * 4;
            const char* ah = wsh + (mb + g) * WROWB + kb;
            uint a0h = *(const uint*)(ah);
            uint a1h = *(const uint*)(ah + 8 * WROWB);
            uint a2h = *(const uint*)(ah + 16);
            uint a3h = *(const uint*)(ah + 8 * WROWB + 16);
            const char* al = wsl + (mb + g) * WROWB + kb;
            uint a0l = *(const uint*)(al);
            uint a1l = *(const uint*)(al + 8 * WROWB);
            uint a2l = *(const uint*)(al + 16);
            uint a3l = *(const uint*)(al + 8 * WROWB + 16);
#pragma unroll
            for (int nt = 0; nt < 10; nt++) {
                const char* bp = xh + (rowb[nt] + dl0 + kb);
                uint b0h = *(const uint*)(bp);
                uint b1h = *(const uint*)(bp + 16);
                const char* bq = xl + (rowb[nt] + dl0 + kb);
                uint b0l = *(const uint*)(bq);
                uint b1l = *(const uint*)(bq + 16);
                mma_bf16(acc[nt], a0h, a1h, a2h, a3h, b0h, b1h);
                mma_bf16(acc[nt], a0h, a1h, a2h, a3h, b0l, b1l);
                mma_bf16(acc[nt], a0l, a1l, a2l, a3l, b0h, b1h);
            }
        }
    }

    __syncthreads();   // all phase-A reads complete

    // ---- phase A epilogue: silu -> dense bf16 hi/lo tiles (overlay) ----
    char* dxh = smem;                 // dense [256 px][136 ch] hi
    char* dxl = smem + XP_BYTES;      // dense lo
#pragma unroll
    for (int nt = 0; nt < 10; nt++) {
        int pb = (nh * 10 + nt) * 8 + 2 * t4;
        if (pb < NPIX) {
            int o = mb + g;
            float bv = bdc[o], bv2 = bdc[o + 8];
            split_store(dxh, dxl, pb * XROWB + o * 2,             silu(acc[nt][0] + bv));
            split_store(dxh, dxl, (pb + 1) * XROWB + o * 2,       silu(acc[nt][1] + bv));
            split_store(dxh, dxl, pb * XROWB + (o + 8) * 2,       silu(acc[nt][2] + bv2));
            split_store(dxh, dxl, (pb + 1) * XROWB + (o + 8) * 2, silu(acc[nt][3] + bv2));
        }
    }
    {   // stage c1 weights
        const float4* sh = (const float4*)whc1;
        const float4* sl = (const float4*)wlc1;
        float4* dh = (float4*)wsh;
        float4* dl = (float4*)wsl;
        for (int i = tid; i < WT_BYTES / 16; i += NT3) { dh[i] = sh[i]; dl[i] = sl[i]; }
    }
    __syncthreads();

    // ---- phase B: pointwise c1 ----
    const int rb0 = nh * 80;            // first row of this warp's n-group
    float acc2[10][4];
#pragma unroll
    for (int nt = 0; nt < 10; nt++) {
        acc2[nt][0] = 0.f; acc2[nt][1] = 0.f; acc2[nt][2] = 0.f; acc2[nt][3] = 0.f;
    }

#pragma unroll
    for (int ks = 0; ks < 8; ks++) {
        int kb = ks * 32 + t4 * 4;
        const char* ah = wsh + (mb + g) * WROWB + kb;
        uint a0h = *(const uint*)(ah);
        uint a1h = *(const uint*)(ah + 8 * WROWB);
        uint a2h = *(const uint*)(ah + 16);
        uint a3h = *(const uint*)(ah + 8 * WROWB + 16);
        const char* al = wsl + (mb + g) * WROWB + kb;
        uint a0l = *(const uint*)(al);
        uint a1l = *(const uint*)(al + 8 * WROWB);
        uint a2l = *(const uint*)(al + 16);
        uint a3l = *(const uint*)(al + 8 * WROWB + 16);
        const char* xrh = dxh + (rb0 + g) * XROWB + kb;
        const char* xrl = dxl + (rb0 + g) * XROWB + kb;
#pragma unroll
        for (int nt = 0; nt < 10; nt++) {
            const char* bp = xrh + nt * 8 * XROWB;
            uint b0h = *(const uint*)(bp);
            uint b1h = *(const uint*)(bp + 16);
            const char* bq = xrl + nt * 8 * XROWB;
            uint b0l = *(const uint*)(bq);
            uint b1l = *(const uint*)(bq + 16);
            mma_bf16(acc2[nt], a0h, a1h, a2h, a3h, b0h, b1h);
            mma_bf16(acc2[nt], a0h, a1h, a2h, a3h, b0l, b1l);
            mma_bf16(acc2[nt], a0l, a1l, a2l, a3l, b0h, b1h);
        }
    }

    // ---- phase B epilogue: residual add into xs ----
#pragma unroll
    for (int nt = 0; nt < 10; nt++) {
        int pb = (nh * 10 + nt) * 8 + 2 * t4;
        if (pb < NPIX) {
            int o = mb + g;
            float bv = bc1[o];
            float* dp = xsg + o * PSTR;
            dp[pb] = silu(acc2[nt][0] + bv) + dp[pb];
            if (pb + 1 < NPIX) dp[pb + 1] = silu(acc2[nt][1] + bv) + dp[pb + 1];
            float bv2 = bc1[o + 8];
            float* dq = xsg + (o + 8) * PSTR;
            dq[pb] = silu(acc2[nt][2] + bv2) + dq[pb];
            if (pb + 1 < NPIX) dq[pb + 1] = silu(acc2[nt][3] + bv2) + dq[pb + 1];
        }
    }
}

// ======== fused residual block (768 thr): xs += silu(w2 @ silu(w1 @ xs)) ========
__global__ __launch_bounds__(NT3, 1) void k_res(
    float* __restrict__ xsb,
    const __nv_bfloat16* __restrict__ wh1, const __nv_bfloat16* __restrict__ wl1,
    const float* __restrict__ b1v,
    const __nv_bfloat16* __restrict__ wh2, const __nv_bfloat16* __restrict__ wl2,
    const float* __restrict__ b2v) {
    extern __shared__ char smem[];
    char* dxh = smem;
    char* dxl = smem + XP_BYTES;
    char* wsh = smem + 2 * XP_BYTES;
    char* wsl = wsh + WT_BYTES;
    int b = blockIdx.x, d = blockIdx.y;
    int tid = threadIdx.x, lane = tid & 31, wid = tid >> 5;
    float* xsg = xsb + (size_t)(d * NB + b) * DM * PSTR;

    for (int i = tid * 16; i < 2 * XP_BYTES; i += NT3 * 16)
        *(float4*)(smem + i) = make_float4(0.f, 0.f, 0.f, 0.f);
    __syncthreads();
    for (int idx = tid; idx < DM * NPIX; idx += NT3) {
        int c = idx / NPIX, p = idx - c * NPIX;
        split_store(dxh, dxl, p * XROWB + c * 2, xsg[c * PSTR + p]);
    }
    {
        const float4* sh = (const float4*)wh1;
        const float4* sl = (const float4*)wl1;
        float4* dh = (float4*)wsh;
        float4* dl = (float4*)wsl;
        for (int i = tid; i < WT_BYTES / 16; i += NT3) { dh[i] = sh[i]; dl[i] = sl[i]; }
    }
    __syncthreads();

    const int g  = lane >> 2;
    const int t4 = lane & 3;
    const int mb = (wid & 7) * 16;
    const int nh = wid >> 3;            // 0..2
    const int rb0 = nh * 80;

    float acc[10][4];
#pragma unroll
    for (int nt = 0; nt < 10; nt++) {
        acc[nt][0] = 0.f; acc[nt][1] = 0.f; acc[nt][2] = 0.f; acc[nt][3] = 0.f;
    }

#pragma unroll
    for (int ks = 0; ks < 8; ks++) {
        int kb = ks * 32 + t4 * 4;
        const char* ah = wsh + (mb + g) * WROWB + kb;
        uint a0h = *(const uint*)(ah);
        uint a1h = *(const uint*)(ah + 8 * WROWB);
        uint a2h = *(const uint*)(ah + 16);
        uint a3h = *(const uint*)(ah + 8 * WROWB + 16);
        const char* al = wsl + (mb + g) * WROWB + kb;
        uint a0l = *(const uint*)(al);
        uint a1l = *(const uint*)(al + 8 * WROWB);
        uint a2l = *(const uint*)(al + 16);
        uint a3l = *(const uint*)(al + 8 * WROWB + 16);
        const char* xrh = dxh + (rb0 + g) * XROWB + kb;
        const char* xrl = dxl + (rb0 + g) * XROWB + kb;
#pragma unroll
        for (int nt = 0; nt < 10; nt++) {
            const char* bp = xrh + nt * 8 * XROWB;
            uint b0h = *(const uint*)(bp);
            uint b1h = *(const uint*)(bp + 16);
            const char* bq = xrl + nt * 8 * XROWB;
            uint b0l = *(const uint*)(bq);
            uint b1l = *(const uint*)(bq + 16);
            mma_bf16(acc[nt], a0h, a1h, a2h, a3h, b0h, b1h);
            mma_bf16(acc[nt], a0h, a1h, a2h, a3h, b0l, b1l);
            mma_bf16(acc[nt], a0l, a1l, a2l, a3l, b0h, b1h);
        }
    }

    __syncthreads();   // mainloop1 reads complete

    // epilogue1: silu -> overwrite the same tiles
#pragma unroll
    for (int nt = 0; nt < 10; nt++) {
        int pb = (nh * 10 + nt) * 8 + 2 * t4;
        if (pb < NPIX) {
            int o = mb + g;
            float bv = b1v[o], bv2 = b1v[o + 8];
            split_store(dxh, dxl, pb * XROWB + o * 2,             silu(acc[nt][0] + bv));
            if (pb + 1 < NPIX)
                split_store(dxh, dxl, (pb + 1) * XROWB + o * 2,   silu(acc[nt][1] + bv));
            split_store(dxh, dxl, pb * XROWB + (o + 8) * 2,       silu(acc[nt][2] + bv2));
            if (pb + 1 < NPIX)
                split_store(dxh, dxl, (pb + 1) * XROWB + (o + 8) * 2, silu(acc[nt][3] + bv2));
        }
    }
    {
        const float4* sh = (const float4*)wh2;
        const float4* sl = (const float4*)wl2;
        float4* dh = (float4*)wsh;
        float4* dl = (float4*)wsl;
        for (int i = tid; i < WT_BYTES / 16; i += NT3) { dh[i] = sh[i]; dl[i] = sl[i]; }
    }
    __syncthreads();

    float acc2[10][4];
#pragma unroll
    for (int nt = 0; nt < 10; nt++) {
        acc2[nt][0] = 0.f; acc2[nt][1] = 0.f; acc2[nt][2] = 0.f; acc2[nt][3] = 0.f;
    }

#pragma unroll
    for (int ks = 0; ks < 8; ks++) {
        int kb = ks * 32 + t4 * 4;
        const char* ah = wsh + (mb + g) * WROWB + kb;
        uint a0h = *(const uint*)(ah);
        uint a1h = *(const uint*)(ah + 8 * WROWB);
        uint a2h = *(const uint*)(ah + 16);
        uint a3h = *(const uint*)(ah + 8 * WROWB + 16);
        const char* al = wsl + (mb + g) * WROWB + kb;
        uint a0l = *(const uint*)(al);
        uint a1l = *(const uint*)(al + 8 * WROWB);
        uint a2l = *(const uint*)(al + 16);
        uint a3l = *(const uint*)(al + 8 * WROWB + 16);
        const char* xrh = dxh + (rb0 + g) * XROWB + kb;
        const char* xrl = dxl + (rb0 + g) * XROWB + kb;
#pragma unroll
        for (int nt = 0; nt < 10; nt++) {
            const char* bp = xrh + nt * 8 * XROWB;
            uint b0h = *(const uint*)(bp);
            uint b1h = *(const uint*)(bp + 16);
            const char* bq = xrl + nt * 8 * XROWB;
            uint b0l = *(const uint*)(bq);
            uint b1l = *(const uint*)(bq + 16);
            mma_bf16(acc2[nt], a0h, a1h, a2h, a3h, b0h, b1h);
            mma_bf16(acc2[nt], a0h, a1h, a2h, a3h, b0l, b1l);
            mma_bf16(acc2[nt], a0l, a1l, a2l, a3l, b0h, b1h);
        }
    }

#pragma unroll
    for (int nt = 0; nt < 10; nt++) {
        int pb = (nh * 10 + nt) * 8 + 2 * t4;
        if (pb < NPIX) {
            int o = mb + g;
            float bv = b2v[o];
            float* dp = xsg + o * PSTR;
            dp[pb] = silu(acc2[nt][0] + bv) + dp[pb];
            if (pb + 1 < NPIX) dp[pb + 1] = silu(acc2[nt][1] + bv) + dp[pb + 1];
            float bv2 = b2v[o + 8];
            float* dq = xsg + (o + 8) * PSTR;
            dq[pb] = silu(acc2[nt][2] + bv2) + dq[pb];
            if (pb + 1 < NPIX) dq[pb + 1] = silu(acc2[nt][3] + bv2) + dq[pb + 1];
        }
    }
}

// -------- tensor-core fin conv 128->64, linear epilogue (R13 proven, 512 thr) --------
__global__ __launch_bounds__(512, 1) void k_fin64(
    const float* __restrict__ srcb, float* __restrict__ dstb,
    const __nv_bfloat16* __restrict__ wh,   // rows 0..63 valid
    const __nv_bfloat16* __restrict__ wl,
    const float* __restrict__ bias) {
    extern __shared__ char smem[];
    char* xh  = smem;
    char* xl  = smem + XP_BYTES;
    char* wsh = smem + 2 * XP_BYTES;
    char* wsl = wsh + WT64_BYTES;
    int b = blockIdx.x, d = blockIdx.y;
    int tid = threadIdx.x, lane = tid & 31, wid = tid >> 5;
    const float* src = srcb + (size_t)(d * NB + b) * DM * PSTR;
    float*       dst = dstb + (size_t)(d * NB + b) * DOUT * PSTR;

    for (int i = tid * 16; i < 2 * XP_BYTES; i += 512 * 16)
        *(float4*)(smem + i) = make_float4(0.f, 0.f, 0.f, 0.f);
    __syncthreads();
    for (int idx = tid; idx < DM * NPIX; idx += 512) {
        int c = idx / NPIX, p = idx - c * NPIX;
        split_store(xh, xl, p * XROWB + c * 2, src[c * PSTR + p]);
    }
    {
        const float4* sh = (const float4*)wh;
        const float4* sl = (const float4*)wl;
        float4* dh = (float4*)wsh;
        float4* dl = (float4*)wsl;
        for (int i = tid; i < WT64_BYTES / 16; i += 512) { dh[i] = sh[i]; dl[i] = sl[i]; }
    }
    __syncthreads();

    const int g  = lane >> 2;
    const int t4 = lane & 3;
    const int mb = (wid & 3) * 16;
    const int nh = wid >> 2;
    const int pb0 = nh * 64;

    float acc[8][4];
#pragma unroll
    for (int nt = 0; nt < 8; nt++) {
        acc[nt][0] = 0.f; acc[nt][1] = 0.f; acc[nt][2] = 0.f; acc[nt][3] = 0.f;
    }

#pragma unroll
    for (int ks = 0; ks < 8; ks++) {
        int kb = ks * 32 + t4 * 4;
        const char* ah = wsh + (mb + g) * WROWB + kb;
        uint a0h = *(const uint*)(ah);
        uint a1h = *(const uint*)(ah + 8 * WROWB);
        uint a2h = *(const uint*)(ah + 16);
        uint a3h = *(const uint*)(ah + 8 * WROWB + 16);
        const char* al = wsl + (mb + g) * WROWB + kb;
        uint a0l = *(const uint*)(al);
        uint a1l = *(const uint*)(al + 8 * WROWB);
        uint a2l = *(const uint*)(al + 16);
        uint a3l = *(const uint*)(al + 8 * WROWB + 16);
        const char* xrh = xh + (pb0 + g) * XROWB + kb;
        const char* xrl = xl + (pb0 + g) * XROWB + kb;
#pragma unroll
        for (int nt = 0; nt < 8; nt++) {
            const char* bp = xrh + nt * 8 * XROWB;
            uint b0h = *(const uint*)(bp);
            uint b1h = *(const uint*)(bp + 16);
            const char* bq = xrl + nt * 8 * XROWB;
            uint b0l = *(const uint*)(bq);
            uint b1l = *(const uint*)(bq + 16);
            mma_bf16(acc[nt], a0h, a1h, a2h, a3h, b0h, b1h);
            mma_bf16(acc[nt], a0h, a1h, a2h, a3h, b0l, b1l);
            mma_bf16(acc[nt], a0l, a1l, a2l, a3l, b0h, b1h);
        }
    }

#pragma unroll
    for (int nt = 0; nt < 8; nt++) {
        int pb = pb0 + nt * 8 + 2 * t4;
        if (pb < NPIX) {
            int o = mb + g;
            float bv = bias[o];
            float* dp = dst + o * PSTR;
            dp[pb] = acc[nt][0] + bv;
            if (pb + 1 < NPIX) dp[pb + 1] = acc[nt][1] + bv;
            float bv2 = bias[o + 8];
            float* dq = dst + (o + 8) * PSTR;
            dq[pb] = acc[nt][2] + bv2;
            if (pb + 1 < NPIX) dq[pb + 1] = acc[nt][3] + bv2;
        }
    }
}

// -------- heads: tanh-clamp + sum dirs + prelu/4, then policy + value (R13 proven) --------
__global__ __launch_bounds__(256, 1) void k_heads(
    const float* __restrict__ finb,   // [4][NB][DOUT][PSTR]
    const float* __restrict__ prelu,
    const float* __restrict__ pdww, const float* __restrict__ pdwb,
    const float* __restrict__ ppw,
    const float* __restrict__ vl1w, const float* __restrict__ vl1b,
    const float* __restrict__ vl2w, const float* __restrict__ vl2b,
    const float* __restrict__ vlfw, const float* __restrict__ vlfb,
    const float* __restrict__ pscale, const float* __restrict__ vscale,
    float* __restrict__ out) {
    extern __shared__ float facc[];   // DOUT*PADP
    __shared__ float vbuf[32], h1[32], h2[32];
    int b = blockIdx.x, tid = threadIdx.x, lane = tid & 31, wid = tid >> 5;

    for (int i = tid; i < DOUT * PADP; i += 256) facc[i] = 0.f;
    __syncthreads();

    for (int idx = tid; idx < DOUT * NPIX; idx += 256) {
        int o = idx / NPIX, p = idx - o * NPIX;
        float s = 0.f;
#pragma unroll
        for (int d = 0; d < 4; d++) {
            float v = finb[((size_t)(d * NB + b) * DOUT + o) * PSTR + p];
            s += MAXF * tanhf(v * INV_MAXF);
        }
        s = (s >= 0.f ? s : prelu[o] * s) * 0.25f;
        int h = p / 15, w = p - h * 15;
        facc[o * PADP + (h + 1) * 17 + w + 1] = s;
    }
    __syncthreads();

    if (tid < NPIX) {
        int h = tid / 15, w = tid - h * 15;
        int base = (h + 1) * 17 + (w + 1);
        float acc = 0.f;
        for (int c = 0; c < DP; c++) {
            const float* fc = facc + c * PADP + base;
            const float* wk = pdww + c * 9;
            float s = pdwb[c];
#pragma unroll
            for (int r = 0; r < 3; r++)
#pragma unroll
                for (int cc = 0; cc < 3; cc++)
                    s += wk[r * 3 + cc] * fc[(r - 1) * 17 + (cc - 1)];
            s = (s >= 0.f) ? s : s * 0.0625f;
            s = fminf(fmaxf(s, -MAXF), MAXF);
            acc += ppw[c] * s;
        }
        acc = (acc >= 0.f) ? acc : acc * 0.0625f;
        out[NB * 3 + (size_t)b * NPIX + tid] = acc * pscale[0];
    }
    __syncthreads();

    if (wid == 0) {
        const float* fc = facc + (DP + lane) * PADP;
        float s = 0.f;
        for (int h = 0; h < 15; h++)
#pragma unroll
            for (int w = 0; w < 15; w++) s += fc[(h + 1) * 17 + w + 1];
        vbuf[lane] = fmaxf(s * (1.f / 225.f), 0.f);
        __syncwarp();
        float a = vl1b[lane];
        for (int i = 0; i < 32; i++) a += vl1w[lane * 32 + i] * vbuf[i];
        h1[lane] = fminf(fmaxf(a, 0.f), MAXM);
        __syncwarp();
        float g = vl2b[lane];
        for (int i = 0; i < 32; i++) g += vl2w[lane * 32 + i] * h1[i];
        h2[lane] = fminf(fmaxf(g, 0.f), MAXM);
        __syncwarp();
        if (lane < 3) {
            float o = vlfb[lane];
            for (int i = 0; i < 32; i++) o += vlfw[lane * 32 + i] * h2[i];
            out[(size_t)b * 3 + lane] = o * vscale[0];
        }
    }
}

// ---------------- host ----------------
extern "C" void kernel_launch(void* const* d_in, const int* in_sizes, int n_in,
                              void* d_out, int out_size) {
    const float* x       = (const float*)d_in[0];
    const float* map_w   = (const float*)d_in[1];
    const float* map_b   = (const float*)d_in[2];
    const float* dconv_w = (const float*)d_in[3];
    const float* dconv_b = (const float*)d_in[4];
    const float* c1_w    = (const float*)d_in[5];
    const float* c1_b    = (const float*)d_in[6];
    const float* r0_w1   = (const float*)d_in[7];
    const float* r0_b1   = (const float*)d_in[8];
    const float* r0_w2   = (const float*)d_in[9];
    const float* r0_b2   = (const float*)d_in[10];
    const float* fin_w   = (const float*)d_in[11];
    const float* fin_b   = (const float*)d_in[12];
    const float* prelu_w = (const float*)d_in[13];
    const float* pdw_w   = (const float*)d_in[14];
    const float* pdw_b   = (const float*)d_in[15];
    const float* ppw_w   = (const float*)d_in[16];
    const float* vl1_w   = (const float*)d_in[17];
    const float* vl1_b   = (const float*)d_in[18];
    const float* vl2_w   = (const float*)d_in[19];
    const float* vl2_b   = (const float*)d_in[20];
    const float* vlf_w   = (const float*)d_in[21];
    const float* vlf_b   = (const float*)d_in[22];
    const float* pscale  = (const float*)d_in[23];
    const float* vscale  = (const float*)d_in[24];
    float* out = (float*)d_out;

    float *xs, *tmp;
    __nv_bfloat16 *wh, *wl;
    cudaGetSymbolAddress((void**)&xs,  g_xs);
    cudaGetSymbolAddress((void**)&tmp, g_tmp);
    cudaGetSymbolAddress((void**)&wh,  g_wh);
    cudaGetSymbolAddress((void**)&wl,  g_wl);

    cudaFuncSetAttribute(k_layer, cudaFuncAttributeMaxDynamicSharedMemorySize, SMD);
    cudaFuncSetAttribute(k_res,   cudaFuncAttributeMaxDynamicSharedMemorySize, SMP);
    cudaFuncSetAttribute(k_fin64, cudaFuncAttributeMaxDynamicSharedMemorySize, SMF);
    cudaFuncSetAttribute(k_heads, cudaFuncAttributeMaxDynamicSharedMemorySize, SMH);

    const int MS = 128 * 136;

    k_prep<<<256, 256>>>(dconv_w, c1_w, r0_w1, r0_w2, fin_w, wh, wl);   // 1
    k_map<<<dim3(NB, 4), 256>>>(x, map_w, map_b, xs);                   // 2

    dim3 gbd(NB, 4);
    for (int l = 0; l < 4; l++)                                         // 3-6
        k_layer<<<gbd, NT3, SMD>>>(xs, wh + l * 3 * MS, wl + l * 3 * MS,
                                   dconv_b + l * DM,
                                   wh + (12 + l) * MS, wl + (12 + l) * MS,
                                   c1_b + l * DM);
    k_res<<<gbd, NT3, SMP>>>(xs, wh + 16 * MS, wl + 16 * MS, r0_b1,     // 7
                             wh + 17 * MS, wl + 17 * MS, r0_b2);

    k_fin64<<<gbd, 512, SMF>>>(xs, tmp, wh + 18 * MS, wl + 18 * MS, fin_b); // 8
    k_heads<<<NB, 256, SMH>>>(tmp, prelu_w, pdw_w, pdw_b, ppw_w,            // 9
                              vl1_w, vl1_b, vl2_w, vl2_b, vlf_w, vlf_b,
                              pscale, vscale, out);
}